// round 14
// baseline (speedup 1.0000x reference)
#include <cuda_runtime.h>
#include <cuda_bf16.h>
#include <cstdint>

#define NN 50000
#define EE 600000
#define D 128
#define HH 8

// ---------------- scratch (device globals) ----------------
__device__ __nv_bfloat16 g_hH [(size_t)NN * D];
__device__ __nv_bfloat16 g_hL [(size_t)NN * D];
__device__ float g_qkvs[(size_t)NN * 512];         // q|k|v|skip
__device__ float g_z   [(size_t)NN * HH];
__device__ float g_acc [(size_t)NN * D];
__device__ float g_x2  [(size_t)NN * D];
__device__ __nv_bfloat16 g_h2H[(size_t)NN * D];
__device__ __nv_bfloat16 g_h2L[(size_t)NN * D];
__device__ __nv_bfloat16 g_uH [(size_t)NN * 4 * D];
__device__ __nv_bfloat16 g_uL [(size_t)NN * 4 * D];

// preconverted transposed weights, bf16 hi/lo, [n][k]
#define OFF_WQ 0
#define OFF_WE 65536
#define OFF_W1 81920
#define OFF_W2 147456
#define BT_TOTAL 212992
__device__ __nv_bfloat16 g_BtH[BT_TOTAL];
__device__ __nv_bfloat16 g_BtL[BT_TOTAL];
__device__ float g_bqkvs[512];

__device__ __forceinline__ int clampi(int v, int lo, int hi) {
    return v < lo ? lo : (v > hi ? hi : v);
}
__device__ __forceinline__ void red_v4(float* ptr, float a, float b, float c, float d) {
    asm volatile("red.global.v4.f32.add [%0], {%1,%2,%3,%4};"
                 :: "l"(ptr), "f"(a), "f"(b), "f"(c), "f"(d) : "memory");
}

// ---------------- mma helpers (sm_80+ PTX, arch-agnostic) ----------------
__device__ __forceinline__ uint32_t smem_u32(const void* p) {
    uint32_t a;
    asm("{ .reg .u64 t; cvta.to.shared.u64 t, %1; cvt.u32.u64 %0, t; }" : "=r"(a) : "l"(p));
    return a;
}
__device__ __forceinline__ void ldm_x4(uint32_t (&r)[4], uint32_t addr) {
    asm volatile("ldmatrix.sync.aligned.m8n8.x4.shared.b16 {%0,%1,%2,%3}, [%4];"
                 : "=r"(r[0]), "=r"(r[1]), "=r"(r[2]), "=r"(r[3]) : "r"(addr));
}
__device__ __forceinline__ void ldm_x2(uint32_t (&r)[2], uint32_t addr) {
    asm volatile("ldmatrix.sync.aligned.m8n8.x2.shared.b16 {%0,%1}, [%2];"
                 : "=r"(r[0]), "=r"(r[1]) : "r"(addr));
}
__device__ __forceinline__ void mma_bf16(float (&d)[4], const uint32_t (&a)[4],
                                         const uint32_t (&b)[2]) {
    asm volatile("mma.sync.aligned.m16n8k16.row.col.f32.bf16.bf16.f32 "
                 "{%0,%1,%2,%3}, {%4,%5,%6,%7}, {%8,%9}, {%0,%1,%2,%3};"
                 : "+f"(d[0]), "+f"(d[1]), "+f"(d[2]), "+f"(d[3])
                 : "r"(a[0]), "r"(a[1]), "r"(a[2]), "r"(a[3]), "r"(b[0]), "r"(b[1]));
}
// fp32 pair -> bf16 hi pair + lo pair
__device__ __forceinline__ void hilo2(float a, float b, __nv_bfloat162& h, __nv_bfloat162& l) {
    h = __float22bfloat162_rn(make_float2(a, b));
    float2 back = __bfloat1622float2(h);
    l = __float22bfloat162_rn(make_float2(a - back.x, b - back.y));
}

// ---------------- K0: preconvert weights + biases ----------------
__global__ void k_preconv(const float* __restrict__ Wq, const float* __restrict__ Wk,
                          const float* __restrict__ Wv, const float* __restrict__ Ws,
                          const float* __restrict__ We, const float* __restrict__ W1,
                          const float* __restrict__ W2,
                          const float* __restrict__ bq, const float* __restrict__ bk,
                          const float* __restrict__ bv, const float* __restrict__ bs) {
    int i = blockIdx.x * 256 + threadIdx.x;
    if (i < 512) {
        int w = i >> 7, j = i & 127;
        g_bqkvs[i] = (w == 0) ? bq[j] : (w == 1) ? bk[j] : (w == 2) ? bv[j] : bs[j];
    }
    if (i >= BT_TOTAL) return;
    float x;
    if (i < 65536) {
        int w = i >> 14, rem = i & 16383, nn = rem >> 7, kk = rem & 127;
        const float* W = (w == 0) ? Wq : (w == 1) ? Wk : (w == 2) ? Wv : Ws;
        x = W[kk * 128 + nn];
    } else if (i < 81920) {
        int rem = i - 65536, nn = rem >> 7, kk = rem & 127;
        x = We[kk * 128 + nn];
    } else if (i < 147456) {
        int rem = i - 81920, nn = rem >> 7, kk = rem & 127;
        x = W1[kk * 512 + nn];
    } else {
        int rem = i - 147456, nn = rem >> 9, kk = rem & 511;
        x = W2[kk * 128 + nn];
    }
    __nv_bfloat16 h = __float2bfloat16(x);
    g_BtH[i] = h;
    g_BtL[i] = __float2bfloat16(x - __bfloat162float(h));
}

// ---------------- generic dense GEMM with bf16 hi/lo inputs (R11-proven) ----------
#define DST 72
#define DENSE_SMEM 73728
__global__ void __launch_bounds__(256) k_dense_bf(
        const __nv_bfloat16* __restrict__ AH, const __nv_bfloat16* __restrict__ AL, int As,
        const __nv_bfloat16* __restrict__ BtHb, const __nv_bfloat16* __restrict__ BtLb,
        int K, const float* __restrict__ bias,
        float* __restrict__ Out, __nv_bfloat16* __restrict__ OutH,
        __nv_bfloat16* __restrict__ OutL, int Os,
        const float* __restrict__ resid, int epi, int M) {
    extern __shared__ char sm[];
    __nv_bfloat16* Ah = (__nv_bfloat16*)sm;
    __nv_bfloat16* Al = (__nv_bfloat16*)(sm + 18432);
    __nv_bfloat16* Bh = (__nv_bfloat16*)(sm + 36864);
    __nv_bfloat16* Bl = (__nv_bfloat16*)(sm + 55296);
    int tx = threadIdx.x, w = tx >> 5, lane = tx & 31;
    int row0 = blockIdx.x * 128, n0 = blockIdx.y * 128;
    const __nv_bfloat16* BH = BtHb + (size_t)n0 * K;
    const __nv_bfloat16* BL = BtLb + (size_t)n0 * K;
    float acc[16][4];
#pragma unroll
    for (int nt = 0; nt < 16; ++nt) {
        acc[nt][0] = 0.f; acc[nt][1] = 0.f; acc[nt][2] = 0.f; acc[nt][3] = 0.f;
    }
    int arow = w * 16 + (lane & 15);
    int acol = (lane >> 4) << 3;
    int brl = lane & 7, bcol = (lane & 8) ? 8 : 0;

    for (int kc = 0; kc < K; kc += 64) {
        __syncthreads();
        for (int i = tx; i < 2048; i += 256) {       // A: 128 rows x 64 k, hi+lo
            int half = i >> 10, j = i & 1023;
            int r = j >> 3, k8 = (j & 7) * 8;
            const __nv_bfloat16* s = half ? AL : AH;
            __nv_bfloat16* d = half ? Al : Ah;
            uint4 val = (row0 + r < M)
                ? *(const uint4*)&s[(size_t)(row0 + r) * As + kc + k8]
                : make_uint4(0u, 0u, 0u, 0u);
            *(uint4*)&d[r * DST + k8] = val;
        }
        for (int i = tx; i < 2048; i += 256) {       // B: 128 n x 64 k, hi+lo
            int half = i >> 10, j = i & 1023;
            int nr = j >> 3, k8 = (j & 7) * 8;
            const __nv_bfloat16* s = half ? BL : BH;
            __nv_bfloat16* d = half ? Bl : Bh;
            *(uint4*)&d[nr * DST + k8] = *(const uint4*)&s[(size_t)nr * K + kc + k8];
        }
        __syncthreads();
        for (int kt = 0; kt < 4; ++kt) {
            int k0 = kt * 16;
            uint32_t ah[4], al[4];
            ldm_x4(ah, smem_u32(&Ah[arow * DST + k0 + acol]));
            ldm_x4(al, smem_u32(&Al[arow * DST + k0 + acol]));
#pragma unroll
            for (int nt = 0; nt < 16; ++nt) {
                uint32_t bh[2], bl[2];
                ldm_x2(bh, smem_u32(&Bh[(nt * 8 + brl) * DST + k0 + bcol]));
                ldm_x2(bl, smem_u32(&Bl[(nt * 8 + brl) * DST + k0 + bcol]));
                mma_bf16(acc[nt], ah, bh);
                mma_bf16(acc[nt], ah, bl);
                mma_bf16(acc[nt], al, bh);
            }
        }
    }
    int rbase = row0 + w * 16 + (lane >> 2);
    int cb = (lane & 3) * 2;
#pragma unroll
    for (int nt = 0; nt < 16; ++nt) {
        int c = n0 + nt * 8 + cb;
        float b0 = bias[c], b1 = bias[c + 1];
#pragma unroll
        for (int hr = 0; hr < 2; ++hr) {
            int row = rbase + hr * 8;
            if (row < M) {
                float v0 = acc[nt][hr * 2 + 0] + b0;
                float v1 = acc[nt][hr * 2 + 1] + b1;
                if (epi == 1) {                       // silu -> bf16 hi/lo out
                    v0 = v0 / (1.0f + __expf(-v0));
                    v1 = v1 / (1.0f + __expf(-v1));
                    __nv_bfloat162 h2, l2;
                    hilo2(v0, v1, h2, l2);
                    *(__nv_bfloat162*)&OutH[(size_t)row * Os + c] = h2;
                    *(__nv_bfloat162*)&OutL[(size_t)row * Os + c] = l2;
                } else {
                    if (epi == 2) {
                        v0 += resid[(size_t)row * 128 + c];
                        v1 += resid[(size_t)row * 128 + c + 1];
                    }
                    *(float2*)&Out[(size_t)row * Os + c] = make_float2(v0, v1);
                }
            }
        }
    }
}

// ---------------- fused edge pass: C spill to smem, thread-per-half-row epilogue ----
#define EAST 136
#define CST 132
#define EDGE_SMEM 104448
__global__ void __launch_bounds__(256, 2) k_edge_mma(
        const float* __restrict__ ea_g, const int* __restrict__ ei, int E, int n) {
    extern __shared__ char sm[];
    __nv_bfloat16* Ah = (__nv_bfloat16*)sm;                    // 34816
    __nv_bfloat16* Al = (__nv_bfloat16*)(sm + 34816);          // 34816
    __nv_bfloat16* Bh = (__nv_bfloat16*)(sm + 69632);          // 17408
    __nv_bfloat16* Bl = (__nv_bfloat16*)(sm + 87040);          // 17408
    float* C = (float*)sm;                                     // overlays Ah/Al post-MMA
    const __nv_bfloat16* WeTH = g_BtH + OFF_WE;
    const __nv_bfloat16* WeTL = g_BtL + OFF_WE;
    int tx = threadIdx.x, w = tx >> 5, lane = tx & 31;
    int e0 = blockIdx.x * 128;

    // convert EA tile fp32 -> bf16 hi/lo
    for (int idx = tx; idx < 4096; idx += 256) {
        int r = idx >> 5, c4 = idx & 31;
        float4 v = (e0 + r < E) ? ((const float4*)ea_g)[(size_t)(e0 + r) * 32 + c4]
                                : make_float4(0.f, 0.f, 0.f, 0.f);
        __nv_bfloat162 h01, l01, h23, l23;
        hilo2(v.x, v.y, h01, l01);
        hilo2(v.z, v.w, h23, l23);
        __nv_bfloat162* ph = (__nv_bfloat162*)&Ah[r * EAST + c4 * 4];
        ph[0] = h01; ph[1] = h23;
        __nv_bfloat162* pl = (__nv_bfloat162*)&Al[r * EAST + c4 * 4];
        pl[0] = l01; pl[1] = l23;
    }
    int arow = w * 16 + (lane & 15);
    int acol = (lane >> 4) << 3;
    int brl = lane & 7, bcol = (lane & 8) ? 8 : 0;

    float acc[16][4];
#pragma unroll
    for (int nt = 0; nt < 16; ++nt) {
        acc[nt][0] = 0.f; acc[nt][1] = 0.f; acc[nt][2] = 0.f; acc[nt][3] = 0.f;
    }
    for (int h = 0; h < 2; ++h) {
        if (h) __syncthreads();       // all warps done reading B(0)
        for (int i = tx; i < 2048; i += 256) {       // B half: 64 n x 128 k, hi+lo
            int half = i >> 10, j = i & 1023;
            int nr = j >> 4, k8 = (j & 15) * 8;
            const __nv_bfloat16* s = half ? WeTL : WeTH;
            __nv_bfloat16* d = half ? Bl : Bh;
            *(uint4*)&d[nr * EAST + k8] = *(const uint4*)&s[(size_t)(h * 64 + nr) * 128 + k8];
        }
        __syncthreads();
        for (int kt = 0; kt < 8; ++kt) {
            int k0 = kt * 16;
            uint32_t ah[4], al[4];
            ldm_x4(ah, smem_u32(&Ah[arow * EAST + k0 + acol]));
            ldm_x4(al, smem_u32(&Al[arow * EAST + k0 + acol]));
#pragma unroll
            for (int nt = 0; nt < 8; ++nt) {
                uint32_t bh[2], bl[2];
                ldm_x2(bh, smem_u32(&Bh[(nt * 8 + brl) * EAST + k0 + bcol]));
                ldm_x2(bl, smem_u32(&Bl[(nt * 8 + brl) * EAST + k0 + bcol]));
                mma_bf16(acc[h * 8 + nt], ah, bh);
                mma_bf16(acc[h * 8 + nt], ah, bl);
                mma_bf16(acc[h * 8 + nt], al, bh);
            }
        }
    }
    __syncthreads();                 // MMA reads of Ah/Al done; C overlays them

    // spill C fragments (frees accumulators -> low-reg epilogue, 2 CTAs/SM)
    {
        int r0s = w * 16 + (lane >> 2);
        int cbs = (lane & 3) * 2;
#pragma unroll
        for (int nt = 0; nt < 16; ++nt) {
            int c = nt * 8 + cbs;
            *(float2*)&C[r0s * CST + c]       = make_float2(acc[nt][0], acc[nt][1]);
            *(float2*)&C[(r0s + 8) * CST + c] = make_float2(acc[nt][2], acc[nt][3]);
        }
    }
    __syncthreads();

    // epilogue: thread owns (row = tx&127, half = tx>>7): 4 heads, contiguous gathers
    {
        int row = tx & 127, half = tx >> 7;
        int e = e0 + row;
        if (e < E) {
            int src = clampi(ei[e], 0, n - 1);
            int dst = clampi(ei[(size_t)E + e], 0, n - 1);
            const float4* qb = (const float4*)&g_qkvs[(size_t)dst * 512 + half * 64];
            const float4* kb = (const float4*)&g_qkvs[(size_t)src * 512 + 128 + half * 64];
            const float4* vb = (const float4*)&g_qkvs[(size_t)src * 512 + 256 + half * 64];
            const float* crow = &C[row * CST + half * 64];
            float* accp = &g_acc[(size_t)dst * 128 + half * 64];
            float pz[4];
#pragma unroll
            for (int hd = 0; hd < 4; ++hd) {
                float logit = 0.f;
                float pv[16];
#pragma unroll
                for (int j = 0; j < 4; ++j) {
                    float4 ee = *(const float4*)&crow[hd * 16 + j * 4];
                    float4 kq = kb[hd * 4 + j];
                    float4 qq = qb[hd * 4 + j];
                    float4 vv = vb[hd * 4 + j];
                    logit = fmaf(qq.x, kq.x + ee.x, logit);
                    logit = fmaf(qq.y, kq.y + ee.y, logit);
                    logit = fmaf(qq.z, kq.z + ee.z, logit);
                    logit = fmaf(qq.w, kq.w + ee.w, logit);
                    pv[j * 4 + 0] = vv.x + ee.x;
                    pv[j * 4 + 1] = vv.y + ee.y;
                    pv[j * 4 + 2] = vv.z + ee.z;
                    pv[j * 4 + 3] = vv.w + ee.w;
                }
                float p = __expf(logit * 0.25f);   // 1/sqrt(16); shift-invariant softmax
                pz[hd] = p;
#pragma unroll
                for (int j = 0; j < 4; ++j)
                    red_v4(accp + hd * 16 + j * 4,
                           p * pv[j * 4 + 0], p * pv[j * 4 + 1],
                           p * pv[j * 4 + 2], p * pv[j * 4 + 3]);
            }
            red_v4(&g_z[(size_t)dst * HH + half * 4], pz[0], pz[1], pz[2], pz[3]);
        }
    }
}

// ---------------- K1: LayerNorm1 -> bf16 hi/lo, plus zero-init acc/z ----------------
__global__ void k_ln1(const float* __restrict__ x, const float* __restrict__ g,
                      const float* __restrict__ b, int n) {
    int row = blockIdx.x * 8 + (threadIdx.x >> 5);
    if (row >= n) return;
    int lane = threadIdx.x & 31;
    ((float4*)g_acc)[(size_t)row * 32 + lane] = make_float4(0.f, 0.f, 0.f, 0.f);
    if (lane < 8) g_z[(size_t)row * HH + lane] = 0.f;

    float4 v = ((const float4*)x)[(size_t)row * 32 + lane];
    float s  = v.x + v.y + v.z + v.w;
    float ss = fmaf(v.x, v.x, fmaf(v.y, v.y, fmaf(v.z, v.z, v.w * v.w)));
#pragma unroll
    for (int o = 16; o > 0; o >>= 1) {
        s  += __shfl_xor_sync(0xFFFFFFFFu, s, o);
        ss += __shfl_xor_sync(0xFFFFFFFFu, ss, o);
    }
    float mu  = s * (1.0f / 128.0f);
    float var = ss * (1.0f / 128.0f) - mu * mu;
    float r   = rsqrtf(var + 1e-5f);
    float4 gg = ((const float4*)g)[lane];
    float4 bb = ((const float4*)b)[lane];
    float o0 = (v.x - mu) * r * gg.x + bb.x;
    float o1 = (v.y - mu) * r * gg.y + bb.y;
    float o2 = (v.z - mu) * r * gg.z + bb.z;
    float o3 = (v.w - mu) * r * gg.w + bb.w;
    __nv_bfloat162 h01, l01, h23, l23;
    hilo2(o0, o1, h01, l01);
    hilo2(o2, o3, h23, l23);
    size_t base = (size_t)row * 128 + lane * 4;
    *(__nv_bfloat162*)&g_hH[base]     = h01;
    *(__nv_bfloat162*)&g_hH[base + 2] = h23;
    *(__nv_bfloat162*)&g_hL[base]     = l01;
    *(__nv_bfloat162*)&g_hL[base + 2] = l23;
}

// ---------------- K7: residual + LN2 -> x2 fp32, h2 bf16 hi/lo ----------------
__global__ void k_resid_ln2(const float* __restrict__ x, const float* __restrict__ alpha,
                            const float* __restrict__ g2, const float* __restrict__ b2,
                            int n) {
    int row = blockIdx.x * 8 + (threadIdx.x >> 5);
    if (row >= n) return;
    int lane = threadIdx.x & 31;
    float a = alpha[0];
    float4 xv = ((const float4*)x)[(size_t)row * 32 + lane];
    float4 av = ((const float4*)g_acc)[(size_t)row * 32 + lane];
    float4 sv = *(const float4*)&g_qkvs[(size_t)row * 512 + 384 + lane * 4];
    float inv = 1.0f / (g_z[(size_t)row * HH + (lane >> 2)] + 1e-16f);
    float4 o;
    o.x = xv.x + a * (av.x * inv + sv.x);
    o.y = xv.y + a * (av.y * inv + sv.y);
    o.z = xv.z + a * (av.z * inv + sv.z);
    o.w = xv.w + a * (av.w * inv + sv.w);
    ((float4*)g_x2)[(size_t)row * 32 + lane] = o;
    float s  = o.x + o.y + o.z + o.w;
    float ss = fmaf(o.x, o.x, fmaf(o.y, o.y, fmaf(o.z, o.z, o.w * o.w)));
#pragma unroll
    for (int off = 16; off > 0; off >>= 1) {
        s  += __shfl_xor_sync(0xFFFFFFFFu, s, off);
        ss += __shfl_xor_sync(0xFFFFFFFFu, ss, off);
    }
    float mu  = s * (1.0f / 128.0f);
    float var = ss * (1.0f / 128.0f) - mu * mu;
    float r   = rsqrtf(var + 1e-5f);
    float4 gg = ((const float4*)g2)[lane];
    float4 bb = ((const float4*)b2)[lane];
    float o0 = (o.x - mu) * r * gg.x + bb.x;
    float o1 = (o.y - mu) * r * gg.y + bb.y;
    float o2 = (o.z - mu) * r * gg.z + bb.z;
    float o3 = (o.w - mu) * r * gg.w + bb.w;
    __nv_bfloat162 h01, l01, h23, l23;
    hilo2(o0, o1, h01, l01);
    hilo2(o2, o3, h23, l23);
    size_t base = (size_t)row * 128 + lane * 4;
    *(__nv_bfloat162*)&g_h2H[base]     = h01;
    *(__nv_bfloat162*)&g_h2H[base + 2] = h23;
    *(__nv_bfloat162*)&g_h2L[base]     = l01;
    *(__nv_bfloat162*)&g_h2L[base + 2] = l23;
}

// ---------------- launch ----------------
extern "C" void kernel_launch(void* const* d_in, const int* in_sizes, int n_in,
                              void* d_out, int out_size) {
    const float* x      = (const float*)d_in[0];
    const float* eattr  = (const float*)d_in[1];
    const int*   ei     = (const int*)d_in[2];
    const float* Wq     = (const float*)d_in[3];
    const float* bq     = (const float*)d_in[4];
    const float* Wk     = (const float*)d_in[5];
    const float* bk     = (const float*)d_in[6];
    const float* Wv     = (const float*)d_in[7];
    const float* bv     = (const float*)d_in[8];
    const float* We     = (const float*)d_in[9];
    const float* Wskip  = (const float*)d_in[10];
    const float* bskip  = (const float*)d_in[11];
    const float* W1     = (const float*)d_in[12];
    const float* b1     = (const float*)d_in[13];
    const float* W2     = (const float*)d_in[14];
    const float* b2     = (const float*)d_in[15];
    const float* g1     = (const float*)d_in[16];
    const float* beta1  = (const float*)d_in[17];
    const float* g2     = (const float*)d_in[18];
    const float* beta2  = (const float*)d_in[19];
    const float* alpha  = (const float*)d_in[20];

    int n = in_sizes[0] / D;   // 50000
    int E = in_sizes[1] / D;   // 600000
    float* out = (float*)d_out;

    int rowTiles = (n + 127) / 128;       // 391
    int edgeTiles = (E + 127) / 128;      // 4688

    static bool init_done = false;
    static __nv_bfloat16 *pH, *pL, *phH, *phL, *ph2H, *ph2L, *puH, *puL;
    static float *pqkvs, *px2, *pbias;
    if (!init_done) {
        cudaFuncSetAttribute(k_edge_mma, cudaFuncAttributeMaxDynamicSharedMemorySize,
                             EDGE_SMEM);
        cudaFuncSetAttribute(k_dense_bf, cudaFuncAttributeMaxDynamicSharedMemorySize,
                             DENSE_SMEM);
        cudaGetSymbolAddress((void**)&pH, g_BtH);
        cudaGetSymbolAddress((void**)&pL, g_BtL);
        cudaGetSymbolAddress((void**)&phH, g_hH);
        cudaGetSymbolAddress((void**)&phL, g_hL);
        cudaGetSymbolAddress((void**)&ph2H, g_h2H);
        cudaGetSymbolAddress((void**)&ph2L, g_h2L);
        cudaGetSymbolAddress((void**)&puH, g_uH);
        cudaGetSymbolAddress((void**)&puL, g_uL);
        cudaGetSymbolAddress((void**)&pqkvs, g_qkvs);
        cudaGetSymbolAddress((void**)&px2, g_x2);
        cudaGetSymbolAddress((void**)&pbias, g_bqkvs);
        init_done = true;
    }

    k_preconv<<<(BT_TOTAL + 255) / 256, 256>>>(Wq, Wk, Wv, Wskip, We, W1, W2,
                                               bq, bk, bv, bskip);
    k_ln1<<<(n + 7) / 8, 256>>>(x, g1, beta1, n);

    // fused node projections -> g_qkvs [N][512]
    {
        dim3 grid(rowTiles, 4);
        k_dense_bf<<<grid, 256, DENSE_SMEM>>>(phH, phL, 128, pH + OFF_WQ, pL + OFF_WQ, 128,
                                              pbias, pqkvs, nullptr, nullptr, 512,
                                              nullptr, 0, n);
    }
    k_edge_mma<<<edgeTiles, 256, EDGE_SMEM>>>(eattr, ei, E, n);
    k_resid_ln2<<<(n + 7) / 8, 256>>>(x, alpha, g2, beta2, n);
    {
        dim3 grid(rowTiles, 4);
        k_dense_bf<<<grid, 256, DENSE_SMEM>>>(ph2H, ph2L, 128, pH + OFF_W1, pL + OFF_W1, 128,
                                              b1, nullptr, puH, puL, 512, nullptr, 1, n);
    }
    k_dense_bf<<<rowTiles, 256, DENSE_SMEM>>>(puH, puL, 512, pH + OFF_W2, pL + OFF_W2, 512,
                                              b2, out, nullptr, nullptr, 128, px2, 2, n);
}

// round 15
// speedup vs baseline: 1.2638x; 1.2638x over previous
#include <cuda_runtime.h>
#include <cuda_bf16.h>
#include <cstdint>

#define NN 50000
#define EE 600000
#define D 128
#define HH 8

// ---------------- scratch (device globals) ----------------
__device__ __nv_bfloat16 g_hH [(size_t)NN * D];
__device__ __nv_bfloat16 g_hL [(size_t)NN * D];
__device__ float g_qkvs[(size_t)NN * 512];         // q|k|v|skip
__device__ float g_z   [(size_t)NN * HH];
__device__ float g_acc [(size_t)NN * D];
__device__ float g_x2  [(size_t)NN * D];
__device__ __nv_bfloat16 g_h2H[(size_t)NN * D];
__device__ __nv_bfloat16 g_h2L[(size_t)NN * D];
__device__ __nv_bfloat16 g_uH [(size_t)NN * 4 * D];
__device__ __nv_bfloat16 g_uL [(size_t)NN * 4 * D];

// preconverted transposed weights, bf16 hi/lo, [n][k]
#define OFF_WQ 0
#define OFF_WE 65536
#define OFF_W1 81920
#define OFF_W2 147456
#define BT_TOTAL 212992
__device__ __nv_bfloat16 g_BtH[BT_TOTAL];
__device__ __nv_bfloat16 g_BtL[BT_TOTAL];
__device__ float g_bqkvs[512];

__device__ __forceinline__ int clampi(int v, int lo, int hi) {
    return v < lo ? lo : (v > hi ? hi : v);
}
__device__ __forceinline__ void red_v2(float* ptr, float a, float b) {
    asm volatile("red.global.v2.f32.add [%0], {%1,%2};"
                 :: "l"(ptr), "f"(a), "f"(b) : "memory");
}
__device__ __forceinline__ void red_v4(float* ptr, float a, float b, float c, float d) {
    asm volatile("red.global.v4.f32.add [%0], {%1,%2,%3,%4};"
                 :: "l"(ptr), "f"(a), "f"(b), "f"(c), "f"(d) : "memory");
}

// ---------------- mma helpers (sm_80+ PTX, arch-agnostic) ----------------
__device__ __forceinline__ uint32_t smem_u32(const void* p) {
    uint32_t a;
    asm("{ .reg .u64 t; cvta.to.shared.u64 t, %1; cvt.u32.u64 %0, t; }" : "=r"(a) : "l"(p));
    return a;
}
__device__ __forceinline__ void ldm_x4(uint32_t (&r)[4], uint32_t addr) {
    asm volatile("ldmatrix.sync.aligned.m8n8.x4.shared.b16 {%0,%1,%2,%3}, [%4];"
                 : "=r"(r[0]), "=r"(r[1]), "=r"(r[2]), "=r"(r[3]) : "r"(addr));
}
__device__ __forceinline__ void ldm_x2(uint32_t (&r)[2], uint32_t addr) {
    asm volatile("ldmatrix.sync.aligned.m8n8.x2.shared.b16 {%0,%1}, [%2];"
                 : "=r"(r[0]), "=r"(r[1]) : "r"(addr));
}
__device__ __forceinline__ void mma_bf16(float (&d)[4], const uint32_t (&a)[4],
                                         const uint32_t (&b)[2]) {
    asm volatile("mma.sync.aligned.m16n8k16.row.col.f32.bf16.bf16.f32 "
                 "{%0,%1,%2,%3}, {%4,%5,%6,%7}, {%8,%9}, {%0,%1,%2,%3};"
                 : "+f"(d[0]), "+f"(d[1]), "+f"(d[2]), "+f"(d[3])
                 : "r"(a[0]), "r"(a[1]), "r"(a[2]), "r"(a[3]), "r"(b[0]), "r"(b[1]));
}
// fp32 pair -> bf16 hi pair + lo pair
__device__ __forceinline__ void hilo2(float a, float b, __nv_bfloat162& h, __nv_bfloat162& l) {
    h = __float22bfloat162_rn(make_float2(a, b));
    float2 back = __bfloat1622float2(h);
    l = __float22bfloat162_rn(make_float2(a - back.x, b - back.y));
}

// ---------------- K0: preconvert weights + biases ----------------
__global__ void k_preconv(const float* __restrict__ Wq, const float* __restrict__ Wk,
                          const float* __restrict__ Wv, const float* __restrict__ Ws,
                          const float* __restrict__ We, const float* __restrict__ W1,
                          const float* __restrict__ W2,
                          const float* __restrict__ bq, const float* __restrict__ bk,
                          const float* __restrict__ bv, const float* __restrict__ bs) {
    int i = blockIdx.x * 256 + threadIdx.x;
    if (i < 512) {
        int w = i >> 7, j = i & 127;
        g_bqkvs[i] = (w == 0) ? bq[j] : (w == 1) ? bk[j] : (w == 2) ? bv[j] : bs[j];
    }
    if (i >= BT_TOTAL) return;
    float x;
    if (i < 65536) {
        int w = i >> 14, rem = i & 16383, nn = rem >> 7, kk = rem & 127;
        const float* W = (w == 0) ? Wq : (w == 1) ? Wk : (w == 2) ? Wv : Ws;
        x = W[kk * 128 + nn];
    } else if (i < 81920) {
        int rem = i - 65536, nn = rem >> 7, kk = rem & 127;
        x = We[kk * 128 + nn];
    } else if (i < 147456) {
        int rem = i - 81920, nn = rem >> 7, kk = rem & 127;
        x = W1[kk * 512 + nn];
    } else {
        int rem = i - 147456, nn = rem >> 9, kk = rem & 511;
        x = W2[kk * 128 + nn];
    }
    __nv_bfloat16 h = __float2bfloat16(x);
    g_BtH[i] = h;
    g_BtL[i] = __float2bfloat16(x - __bfloat162float(h));
}

// ---------------- generic dense GEMM with bf16 hi/lo inputs (R11-proven) ----------
#define DST 72
#define DENSE_SMEM 73728
__global__ void __launch_bounds__(256) k_dense_bf(
        const __nv_bfloat16* __restrict__ AH, const __nv_bfloat16* __restrict__ AL, int As,
        const __nv_bfloat16* __restrict__ BtHb, const __nv_bfloat16* __restrict__ BtLb,
        int K, const float* __restrict__ bias,
        float* __restrict__ Out, __nv_bfloat16* __restrict__ OutH,
        __nv_bfloat16* __restrict__ OutL, int Os,
        const float* __restrict__ resid, int epi, int M) {
    extern __shared__ char sm[];
    __nv_bfloat16* Ah = (__nv_bfloat16*)sm;
    __nv_bfloat16* Al = (__nv_bfloat16*)(sm + 18432);
    __nv_bfloat16* Bh = (__nv_bfloat16*)(sm + 36864);
    __nv_bfloat16* Bl = (__nv_bfloat16*)(sm + 55296);
    int tx = threadIdx.x, w = tx >> 5, lane = tx & 31;
    int row0 = blockIdx.x * 128, n0 = blockIdx.y * 128;
    const __nv_bfloat16* BH = BtHb + (size_t)n0 * K;
    const __nv_bfloat16* BL = BtLb + (size_t)n0 * K;
    float acc[16][4];
#pragma unroll
    for (int nt = 0; nt < 16; ++nt) {
        acc[nt][0] = 0.f; acc[nt][1] = 0.f; acc[nt][2] = 0.f; acc[nt][3] = 0.f;
    }
    int arow = w * 16 + (lane & 15);
    int acol = (lane >> 4) << 3;
    int brl = lane & 7, bcol = (lane & 8) ? 8 : 0;

    for (int kc = 0; kc < K; kc += 64) {
        __syncthreads();
        for (int i = tx; i < 2048; i += 256) {       // A: 128 rows x 64 k, hi+lo
            int half = i >> 10, j = i & 1023;
            int r = j >> 3, k8 = (j & 7) * 8;
            const __nv_bfloat16* s = half ? AL : AH;
            __nv_bfloat16* d = half ? Al : Ah;
            uint4 val = (row0 + r < M)
                ? *(const uint4*)&s[(size_t)(row0 + r) * As + kc + k8]
                : make_uint4(0u, 0u, 0u, 0u);
            *(uint4*)&d[r * DST + k8] = val;
        }
        for (int i = tx; i < 2048; i += 256) {       // B: 128 n x 64 k, hi+lo
            int half = i >> 10, j = i & 1023;
            int nr = j >> 3, k8 = (j & 7) * 8;
            const __nv_bfloat16* s = half ? BL : BH;
            __nv_bfloat16* d = half ? Bl : Bh;
            *(uint4*)&d[nr * DST + k8] = *(const uint4*)&s[(size_t)nr * K + kc + k8];
        }
        __syncthreads();
        for (int kt = 0; kt < 4; ++kt) {
            int k0 = kt * 16;
            uint32_t ah[4], al[4];
            ldm_x4(ah, smem_u32(&Ah[arow * DST + k0 + acol]));
            ldm_x4(al, smem_u32(&Al[arow * DST + k0 + acol]));
#pragma unroll
            for (int nt = 0; nt < 16; ++nt) {
                uint32_t bh[2], bl[2];
                ldm_x2(bh, smem_u32(&Bh[(nt * 8 + brl) * DST + k0 + bcol]));
                ldm_x2(bl, smem_u32(&Bl[(nt * 8 + brl) * DST + k0 + bcol]));
                mma_bf16(acc[nt], ah, bh);
                mma_bf16(acc[nt], ah, bl);
                mma_bf16(acc[nt], al, bh);
            }
        }
    }
    int rbase = row0 + w * 16 + (lane >> 2);
    int cb = (lane & 3) * 2;
#pragma unroll
    for (int nt = 0; nt < 16; ++nt) {
        int c = n0 + nt * 8 + cb;
        float b0 = bias[c], b1 = bias[c + 1];
#pragma unroll
        for (int hr = 0; hr < 2; ++hr) {
            int row = rbase + hr * 8;
            if (row < M) {
                float v0 = acc[nt][hr * 2 + 0] + b0;
                float v1 = acc[nt][hr * 2 + 1] + b1;
                if (epi == 1) {                       // silu -> bf16 hi/lo out
                    v0 = v0 / (1.0f + __expf(-v0));
                    v1 = v1 / (1.0f + __expf(-v1));
                    __nv_bfloat162 h2, l2;
                    hilo2(v0, v1, h2, l2);
                    *(__nv_bfloat162*)&OutH[(size_t)row * Os + c] = h2;
                    *(__nv_bfloat162*)&OutL[(size_t)row * Os + c] = l2;
                } else {
                    if (epi == 2) {
                        v0 += resid[(size_t)row * 128 + c];
                        v1 += resid[(size_t)row * 128 + c + 1];
                    }
                    *(float2*)&Out[(size_t)row * Os + c] = make_float2(v0, v1);
                }
            }
        }
    }
}

// ---------------- fused edge pass: per-half register epilogue, 2 CTAs/SM ----------
#define EAST 136
#define EDGE_SMEM 104448
__global__ void __launch_bounds__(256, 2) k_edge_mma(
        const float* __restrict__ ea_g, const int* __restrict__ ei, int E, int n) {
    extern __shared__ char sm[];
    __nv_bfloat16* Ah = (__nv_bfloat16*)sm;                    // 34816
    __nv_bfloat16* Al = (__nv_bfloat16*)(sm + 34816);          // 34816
    __nv_bfloat16* Bh = (__nv_bfloat16*)(sm + 69632);          // 17408
    __nv_bfloat16* Bl = (__nv_bfloat16*)(sm + 87040);          // 17408
    const __nv_bfloat16* WeTH = g_BtH + OFF_WE;
    const __nv_bfloat16* WeTL = g_BtL + OFF_WE;
    int tx = threadIdx.x, w = tx >> 5, lane = tx & 31;
    int e0 = blockIdx.x * 128;

    // convert EA tile fp32 -> bf16 hi/lo
    for (int idx = tx; idx < 4096; idx += 256) {
        int r = idx >> 5, c4 = idx & 31;
        float4 v = (e0 + r < E) ? ((const float4*)ea_g)[(size_t)(e0 + r) * 32 + c4]
                                : make_float4(0.f, 0.f, 0.f, 0.f);
        __nv_bfloat162 h01, l01, h23, l23;
        hilo2(v.x, v.y, h01, l01);
        hilo2(v.z, v.w, h23, l23);
        __nv_bfloat162* ph = (__nv_bfloat162*)&Ah[r * EAST + c4 * 4];
        ph[0] = h01; ph[1] = h23;
        __nv_bfloat162* pl = (__nv_bfloat162*)&Al[r * EAST + c4 * 4];
        pl[0] = l01; pl[1] = l23;
    }
    int arow = w * 16 + (lane & 15);
    int acol = (lane >> 4) << 3;
    int brl = lane & 7, bcol = (lane & 8) ? 8 : 0;
    int cb = (lane & 3) * 2;

    // hoist per-row edge indices (rows owned by this thread's quad)
    int rowA = w * 16 + (lane >> 2);         // rr = 0
    int rowB = rowA + 8;                     // rr = 1
    int eA = e0 + rowA, eB = e0 + rowB;
    bool okA = (eA < E), okB = (eB < E);
    int eAc = okA ? eA : E - 1, eBc = okB ? eB : E - 1;
    int srcA = clampi(ei[eAc], 0, n - 1), dstA = clampi(ei[(size_t)E + eAc], 0, n - 1);
    int srcB = clampi(ei[eBc], 0, n - 1), dstB = clampi(ei[(size_t)E + eBc], 0, n - 1);

    for (int h = 0; h < 2; ++h) {
        if (h) __syncthreads();       // all warps done reading B(0) (MMA(0) complete)
        for (int i = tx; i < 2048; i += 256) {       // B half: 64 n x 128 k, hi+lo
            int half = i >> 10, j = i & 1023;
            int nr = j >> 4, k8 = (j & 15) * 8;
            const __nv_bfloat16* s = half ? WeTL : WeTH;
            __nv_bfloat16* d = half ? Bl : Bh;
            *(uint4*)&d[nr * EAST + k8] = *(const uint4*)&s[(size_t)(h * 64 + nr) * 128 + k8];
        }
        __syncthreads();
        float acc[8][4];
#pragma unroll
        for (int nt = 0; nt < 8; ++nt) {
            acc[nt][0] = 0.f; acc[nt][1] = 0.f; acc[nt][2] = 0.f; acc[nt][3] = 0.f;
        }
        for (int kt = 0; kt < 8; ++kt) {
            int k0 = kt * 16;
            uint32_t ah[4], al[4];
            ldm_x4(ah, smem_u32(&Ah[arow * EAST + k0 + acol]));
            ldm_x4(al, smem_u32(&Al[arow * EAST + k0 + acol]));
#pragma unroll
            for (int nt = 0; nt < 8; ++nt) {
                uint32_t bh[2], bl[2];
                ldm_x2(bh, smem_u32(&Bh[(nt * 8 + brl) * EAST + k0 + bcol]));
                ldm_x2(bl, smem_u32(&Bl[(nt * 8 + brl) * EAST + k0 + bcol]));
                mma_bf16(acc[nt], ah, bh);
                mma_bf16(acc[nt], ah, bl);
                mma_bf16(acc[nt], al, bh);
            }
        }

        // per-half register epilogue (cols h*64 .. h*64+63)
#pragma unroll
        for (int rr = 0; rr < 2; ++rr) {
            bool ok = rr ? okB : okA;
            int src = rr ? srcB : srcA;
            int dst = rr ? dstB : dstA;
            const float* qb = &g_qkvs[(size_t)dst * 512];
            const float* kb = &g_qkvs[(size_t)src * 512 + 128];
            const float* vb = &g_qkvs[(size_t)src * 512 + 256];
            float pz[4];
#pragma unroll
            for (int hd = 0; hd < 4; ++hd) {
                float part = 0.f;
                float pv[4];
#pragma unroll
                for (int t = 0; t < 2; ++t) {
                    int lnt = hd * 2 + t;
                    int gc = h * 64 + lnt * 8 + cb;
                    float e0v = acc[lnt][rr * 2 + 0], e1v = acc[lnt][rr * 2 + 1];
                    float2 kq = *(const float2*)&kb[gc];
                    float2 qq = *(const float2*)&qb[gc];
                    float2 vv = *(const float2*)&vb[gc];
                    part = fmaf(qq.x, kq.x + e0v, part);
                    part = fmaf(qq.y, kq.y + e1v, part);
                    pv[t * 2 + 0] = vv.x + e0v;
                    pv[t * 2 + 1] = vv.y + e1v;
                }
                part += __shfl_xor_sync(0xFFFFFFFFu, part, 1);
                part += __shfl_xor_sync(0xFFFFFFFFu, part, 2);
                float p = __expf(part * 0.25f);   // 1/sqrt(16); shift-invariant softmax
                pz[hd] = p;
                if (ok) {
#pragma unroll
                    for (int t = 0; t < 2; ++t) {
                        int gc = h * 64 + (hd * 2 + t) * 8 + cb;
                        red_v2(&g_acc[(size_t)dst * 128 + gc],
                               p * pv[t * 2], p * pv[t * 2 + 1]);
                    }
                }
            }
            if (ok && (lane & 3) == 0)
                red_v4(&g_z[(size_t)dst * HH + h * 4], pz[0], pz[1], pz[2], pz[3]);
        }
    }
}

// ---------------- K1: LayerNorm1 -> bf16 hi/lo, plus zero-init acc/z ----------------
__global__ void k_ln1(const float* __restrict__ x, const float* __restrict__ g,
                      const float* __restrict__ b, int n) {
    int row = blockIdx.x * 8 + (threadIdx.x >> 5);
    if (row >= n) return;
    int lane = threadIdx.x & 31;
    ((float4*)g_acc)[(size_t)row * 32 + lane] = make_float4(0.f, 0.f, 0.f, 0.f);
    if (lane < 8) g_z[(size_t)row * HH + lane] = 0.f;

    float4 v = ((const float4*)x)[(size_t)row * 32 + lane];
    float s  = v.x + v.y + v.z + v.w;
    float ss = fmaf(v.x, v.x, fmaf(v.y, v.y, fmaf(v.z, v.z, v.w * v.w)));
#pragma unroll
    for (int o = 16; o > 0; o >>= 1) {
        s  += __shfl_xor_sync(0xFFFFFFFFu, s, o);
        ss += __shfl_xor_sync(0xFFFFFFFFu, ss, o);
    }
    float mu  = s * (1.0f / 128.0f);
    float var = ss * (1.0f / 128.0f) - mu * mu;
    float r   = rsqrtf(var + 1e-5f);
    float4 gg = ((const float4*)g)[lane];
    float4 bb = ((const float4*)b)[lane];
    float o0 = (v.x - mu) * r * gg.x + bb.x;
    float o1 = (v.y - mu) * r * gg.y + bb.y;
    float o2 = (v.z - mu) * r * gg.z + bb.z;
    float o3 = (v.w - mu) * r * gg.w + bb.w;
    __nv_bfloat162 h01, l01, h23, l23;
    hilo2(o0, o1, h01, l01);
    hilo2(o2, o3, h23, l23);
    size_t base = (size_t)row * 128 + lane * 4;
    *(__nv_bfloat162*)&g_hH[base]     = h01;
    *(__nv_bfloat162*)&g_hH[base + 2] = h23;
    *(__nv_bfloat162*)&g_hL[base]     = l01;
    *(__nv_bfloat162*)&g_hL[base + 2] = l23;
}

// ---------------- K7: residual + LN2 -> x2 fp32, h2 bf16 hi/lo ----------------
__global__ void k_resid_ln2(const float* __restrict__ x, const float* __restrict__ alpha,
                            const float* __restrict__ g2, const float* __restrict__ b2,
                            int n) {
    int row = blockIdx.x * 8 + (threadIdx.x >> 5);
    if (row >= n) return;
    int lane = threadIdx.x & 31;
    float a = alpha[0];
    float4 xv = ((const float4*)x)[(size_t)row * 32 + lane];
    float4 av = ((const float4*)g_acc)[(size_t)row * 32 + lane];
    float4 sv = *(const float4*)&g_qkvs[(size_t)row * 512 + 384 + lane * 4];
    float inv = 1.0f / (g_z[(size_t)row * HH + (lane >> 2)] + 1e-16f);
    float4 o;
    o.x = xv.x + a * (av.x * inv + sv.x);
    o.y = xv.y + a * (av.y * inv + sv.y);
    o.z = xv.z + a * (av.z * inv + sv.z);
    o.w = xv.w + a * (av.w * inv + sv.w);
    ((float4*)g_x2)[(size_t)row * 32 + lane] = o;
    float s  = o.x + o.y + o.z + o.w;
    float ss = fmaf(o.x, o.x, fmaf(o.y, o.y, fmaf(o.z, o.z, o.w * o.w)));
#pragma unroll
    for (int off = 16; off > 0; off >>= 1) {
        s  += __shfl_xor_sync(0xFFFFFFFFu, s, off);
        ss += __shfl_xor_sync(0xFFFFFFFFu, ss, off);
    }
    float mu  = s * (1.0f / 128.0f);
    float var = ss * (1.0f / 128.0f) - mu * mu;
    float r   = rsqrtf(var + 1e-5f);
    float4 gg = ((const float4*)g2)[lane];
    float4 bb = ((const float4*)b2)[lane];
    float o0 = (o.x - mu) * r * gg.x + bb.x;
    float o1 = (o.y - mu) * r * gg.y + bb.y;
    float o2 = (o.z - mu) * r * gg.z + bb.z;
    float o3 = (o.w - mu) * r * gg.w + bb.w;
    __nv_bfloat162 h01, l01, h23, l23;
    hilo2(o0, o1, h01, l01);
    hilo2(o2, o3, h23, l23);
    size_t base = (size_t)row * 128 + lane * 4;
    *(__nv_bfloat162*)&g_h2H[base]     = h01;
    *(__nv_bfloat162*)&g_h2H[base + 2] = h23;
    *(__nv_bfloat162*)&g_h2L[base]     = l01;
    *(__nv_bfloat162*)&g_h2L[base + 2] = l23;
}

// ---------------- launch ----------------
extern "C" void kernel_launch(void* const* d_in, const int* in_sizes, int n_in,
                              void* d_out, int out_size) {
    const float* x      = (const float*)d_in[0];
    const float* eattr  = (const float*)d_in[1];
    const int*   ei     = (const int*)d_in[2];
    const float* Wq     = (const float*)d_in[3];
    const float* bq     = (const float*)d_in[4];
    const float* Wk     = (const float*)d_in[5];
    const float* bk     = (const float*)d_in[6];
    const float* Wv     = (const float*)d_in[7];
    const float* bv     = (const float*)d_in[8];
    const float* We     = (const float*)d_in[9];
    const float* Wskip  = (const float*)d_in[10];
    const float* bskip  = (const float*)d_in[11];
    const float* W1     = (const float*)d_in[12];
    const float* b1     = (const float*)d_in[13];
    const float* W2     = (const float*)d_in[14];
    const float* b2     = (const float*)d_in[15];
    const float* g1     = (const float*)d_in[16];
    const float* beta1  = (const float*)d_in[17];
    const float* g2     = (const float*)d_in[18];
    const float* beta2  = (const float*)d_in[19];
    const float* alpha  = (const float*)d_in[20];

    int n = in_sizes[0] / D;   // 50000
    int E = in_sizes[1] / D;   // 600000
    float* out = (float*)d_out;

    int rowTiles = (n + 127) / 128;       // 391
    int edgeTiles = (E + 127) / 128;      // 4688

    static bool init_done = false;
    static __nv_bfloat16 *pH, *pL, *phH, *phL, *ph2H, *ph2L, *puH, *puL;
    static float *pqkvs, *px2, *pbias;
    if (!init_done) {
        cudaFuncSetAttribute(k_edge_mma, cudaFuncAttributeMaxDynamicSharedMemorySize,
                             EDGE_SMEM);
        cudaFuncSetAttribute(k_dense_bf, cudaFuncAttributeMaxDynamicSharedMemorySize,
                             DENSE_SMEM);
        cudaGetSymbolAddress((void**)&pH, g_BtH);
        cudaGetSymbolAddress((void**)&pL, g_BtL);
        cudaGetSymbolAddress((void**)&phH, g_hH);
        cudaGetSymbolAddress((void**)&phL, g_hL);
        cudaGetSymbolAddress((void**)&ph2H, g_h2H);
        cudaGetSymbolAddress((void**)&ph2L, g_h2L);
        cudaGetSymbolAddress((void**)&puH, g_uH);
        cudaGetSymbolAddress((void**)&puL, g_uL);
        cudaGetSymbolAddress((void**)&pqkvs, g_qkvs);
        cudaGetSymbolAddress((void**)&px2, g_x2);
        cudaGetSymbolAddress((void**)&pbias, g_bqkvs);
        init_done = true;
    }

    k_preconv<<<(BT_TOTAL + 255) / 256, 256>>>(Wq, Wk, Wv, Wskip, We, W1, W2,
                                               bq, bk, bv, bskip);
    k_ln1<<<(n + 7) / 8, 256>>>(x, g1, beta1, n);

    // fused node projections -> g_qkvs [N][512]
    {
        dim3 grid(rowTiles, 4);
        k_dense_bf<<<grid, 256, DENSE_SMEM>>>(phH, phL, 128, pH + OFF_WQ, pL + OFF_WQ, 128,
                                              pbias, pqkvs, nullptr, nullptr, 512,
                                              nullptr, 0, n);
    }
    k_edge_mma<<<edgeTiles, 256, EDGE_SMEM>>>(eattr, ei, E, n);
    k_resid_ln2<<<(n + 7) / 8, 256>>>(x, alpha, g2, beta2, n);
    {
        dim3 grid(rowTiles, 4);
        k_dense_bf<<<grid, 256, DENSE_SMEM>>>(ph2H, ph2L, 128, pH + OFF_W1, pL + OFF_W1, 128,
                                              b1, nullptr, puH, puL, 512, nullptr, 1, n);
    }
    k_dense_bf<<<rowTiles, 256, DENSE_SMEM>>>(puH, puL, 512, pH + OFF_W2, pL + OFF_W2, 512,
                                              b2, out, nullptr, nullptr, 128, px2, 2, n);
}

// round 16
// speedup vs baseline: 1.3798x; 1.0918x over previous
#include <cuda_runtime.h>
#include <cuda_bf16.h>
#include <cstdint>

#define NN 50000
#define EE 600000
#define D 128
#define HH 8

// ---------------- scratch (device globals) ----------------
__device__ __nv_bfloat16 g_hH [(size_t)NN * D];
__device__ __nv_bfloat16 g_hL [(size_t)NN * D];
__device__ float g_qkvs[(size_t)NN * 512];         // q|k|v|skip
__device__ float g_z   [(size_t)NN * HH];
__device__ float g_acc [(size_t)NN * D];
__device__ float g_x2  [(size_t)NN * D];
__device__ __nv_bfloat16 g_h2H[(size_t)NN * D];
__device__ __nv_bfloat16 g_h2L[(size_t)NN * D];
__device__ __nv_bfloat16 g_uH [(size_t)NN * 4 * D];
__device__ __nv_bfloat16 g_uL [(size_t)NN * 4 * D];

// preconverted transposed weights, bf16 hi/lo, [n][k]
#define OFF_WQ 0
#define OFF_WE 65536
#define OFF_W1 81920
#define OFF_W2 147456
#define BT_TOTAL 212992
__device__ __nv_bfloat16 g_BtH[BT_TOTAL];
__device__ __nv_bfloat16 g_BtL[BT_TOTAL];
__device__ float g_bqkvs[512];

__device__ __forceinline__ int clampi(int v, int lo, int hi) {
    return v < lo ? lo : (v > hi ? hi : v);
}
__device__ __forceinline__ void red_f32(float* ptr, float a) {
    asm volatile("red.global.add.f32 [%0], %1;" :: "l"(ptr), "f"(a) : "memory");
}
__device__ __forceinline__ void red_v4(float* ptr, float a, float b, float c, float d) {
    asm volatile("red.global.v4.f32.add [%0], {%1,%2,%3,%4};"
                 :: "l"(ptr), "f"(a), "f"(b), "f"(c), "f"(d) : "memory");
}

// ---------------- mma helpers (sm_80+ PTX, arch-agnostic) ----------------
__device__ __forceinline__ uint32_t smem_u32(const void* p) {
    uint32_t a;
    asm("{ .reg .u64 t; cvta.to.shared.u64 t, %1; cvt.u32.u64 %0, t; }" : "=r"(a) : "l"(p));
    return a;
}
__device__ __forceinline__ void ldm_x4(uint32_t (&r)[4], uint32_t addr) {
    asm volatile("ldmatrix.sync.aligned.m8n8.x4.shared.b16 {%0,%1,%2,%3}, [%4];"
                 : "=r"(r[0]), "=r"(r[1]), "=r"(r[2]), "=r"(r[3]) : "r"(addr));
}
__device__ __forceinline__ void ldm_x2(uint32_t (&r)[2], uint32_t addr) {
    asm volatile("ldmatrix.sync.aligned.m8n8.x2.shared.b16 {%0,%1}, [%2];"
                 : "=r"(r[0]), "=r"(r[1]) : "r"(addr));
}
__device__ __forceinline__ void mma_bf16(float (&d)[4], const uint32_t (&a)[4],
                                         const uint32_t (&b)[2]) {
    asm volatile("mma.sync.aligned.m16n8k16.row.col.f32.bf16.bf16.f32 "
                 "{%0,%1,%2,%3}, {%4,%5,%6,%7}, {%8,%9}, {%0,%1,%2,%3};"
                 : "+f"(d[0]), "+f"(d[1]), "+f"(d[2]), "+f"(d[3])
                 : "r"(a[0]), "r"(a[1]), "r"(a[2]), "r"(a[3]), "r"(b[0]), "r"(b[1]));
}
// fp32 pair -> bf16 hi pair + lo pair
__device__ __forceinline__ void hilo2(float a, float b, __nv_bfloat162& h, __nv_bfloat162& l) {
    h = __float22bfloat162_rn(make_float2(a, b));
    float2 back = __bfloat1622float2(h);
    l = __float22bfloat162_rn(make_float2(a - back.x, b - back.y));
}

// ---------------- K0: preconvert weights + biases ----------------
__global__ void k_preconv(const float* __restrict__ Wq, const float* __restrict__ Wk,
                          const float* __restrict__ Wv, const float* __restrict__ Ws,
                          const float* __restrict__ We, const float* __restrict__ W1,
                          const float* __restrict__ W2,
                          const float* __restrict__ bq, const float* __restrict__ bk,
                          const float* __restrict__ bv, const float* __restrict__ bs) {
    int i = blockIdx.x * 256 + threadIdx.x;
    if (i < 512) {
        int w = i >> 7, j = i & 127;
        g_bqkvs[i] = (w == 0) ? bq[j] : (w == 1) ? bk[j] : (w == 2) ? bv[j] : bs[j];
    }
    if (i >= BT_TOTAL) return;
    float x;
    if (i < 65536) {
        int w = i >> 14, rem = i & 16383, nn = rem >> 7, kk = rem & 127;
        const float* W = (w == 0) ? Wq : (w == 1) ? Wk : (w == 2) ? Wv : Ws;
        x = W[kk * 128 + nn];
    } else if (i < 81920) {
        int rem = i - 65536, nn = rem >> 7, kk = rem & 127;
        x = We[kk * 128 + nn];
    } else if (i < 147456) {
        int rem = i - 81920, nn = rem >> 7, kk = rem & 127;
        x = W1[kk * 512 + nn];
    } else {
        int rem = i - 147456, nn = rem >> 9, kk = rem & 511;
        x = W2[kk * 128 + nn];
    }
    __nv_bfloat16 h = __float2bfloat16(x);
    g_BtH[i] = h;
    g_BtL[i] = __float2bfloat16(x - __bfloat162float(h));
}

// ---------------- generic dense GEMM with bf16 hi/lo inputs (R11-proven) ----------
#define DST 72
#define DENSE_SMEM 73728
__global__ void __launch_bounds__(256) k_dense_bf(
        const __nv_bfloat16* __restrict__ AH, const __nv_bfloat16* __restrict__ AL, int As,
        const __nv_bfloat16* __restrict__ BtHb, const __nv_bfloat16* __restrict__ BtLb,
        int K, const float* __restrict__ bias,
        float* __restrict__ Out, __nv_bfloat16* __restrict__ OutH,
        __nv_bfloat16* __restrict__ OutL, int Os,
        const float* __restrict__ resid, int epi, int M) {
    extern __shared__ char sm[];
    __nv_bfloat16* Ah = (__nv_bfloat16*)sm;
    __nv_bfloat16* Al = (__nv_bfloat16*)(sm + 18432);
    __nv_bfloat16* Bh = (__nv_bfloat16*)(sm + 36864);
    __nv_bfloat16* Bl = (__nv_bfloat16*)(sm + 55296);
    int tx = threadIdx.x, w = tx >> 5, lane = tx & 31;
    int row0 = blockIdx.x * 128, n0 = blockIdx.y * 128;
    const __nv_bfloat16* BH = BtHb + (size_t)n0 * K;
    const __nv_bfloat16* BL = BtLb + (size_t)n0 * K;
    float acc[16][4];
#pragma unroll
    for (int nt = 0; nt < 16; ++nt) {
        acc[nt][0] = 0.f; acc[nt][1] = 0.f; acc[nt][2] = 0.f; acc[nt][3] = 0.f;
    }
    int arow = w * 16 + (lane & 15);
    int acol = (lane >> 4) << 3;
    int brl = lane & 7, bcol = (lane & 8) ? 8 : 0;

    for (int kc = 0; kc < K; kc += 64) {
        __syncthreads();
        for (int i = tx; i < 2048; i += 256) {       // A: 128 rows x 64 k, hi+lo
            int half = i >> 10, j = i & 1023;
            int r = j >> 3, k8 = (j & 7) * 8;
            const __nv_bfloat16* s = half ? AL : AH;
            __nv_bfloat16* d = half ? Al : Ah;
            uint4 val = (row0 + r < M)
                ? *(const uint4*)&s[(size_t)(row0 + r) * As + kc + k8]
                : make_uint4(0u, 0u, 0u, 0u);
            *(uint4*)&d[r * DST + k8] = val;
        }
        for (int i = tx; i < 2048; i += 256) {       // B: 128 n x 64 k, hi+lo
            int half = i >> 10, j = i & 1023;
            int nr = j >> 3, k8 = (j & 7) * 8;
            const __nv_bfloat16* s = half ? BL : BH;
            __nv_bfloat16* d = half ? Bl : Bh;
            *(uint4*)&d[nr * DST + k8] = *(const uint4*)&s[(size_t)nr * K + kc + k8];
        }
        __syncthreads();
        for (int kt = 0; kt < 4; ++kt) {
            int k0 = kt * 16;
            uint32_t ah[4], al[4];
            ldm_x4(ah, smem_u32(&Ah[arow * DST + k0 + acol]));
            ldm_x4(al, smem_u32(&Al[arow * DST + k0 + acol]));
#pragma unroll
            for (int nt = 0; nt < 16; ++nt) {
                uint32_t bh[2], bl[2];
                ldm_x2(bh, smem_u32(&Bh[(nt * 8 + brl) * DST + k0 + bcol]));
                ldm_x2(bl, smem_u32(&Bl[(nt * 8 + brl) * DST + k0 + bcol]));
                mma_bf16(acc[nt], ah, bh);
                mma_bf16(acc[nt], ah, bl);
                mma_bf16(acc[nt], al, bh);
            }
        }
    }
    int rbase = row0 + w * 16 + (lane >> 2);
    int cb = (lane & 3) * 2;
#pragma unroll
    for (int nt = 0; nt < 16; ++nt) {
        int c = n0 + nt * 8 + cb;
        float b0 = bias[c], b1 = bias[c + 1];
#pragma unroll
        for (int hr = 0; hr < 2; ++hr) {
            int row = rbase + hr * 8;
            if (row < M) {
                float v0 = acc[nt][hr * 2 + 0] + b0;
                float v1 = acc[nt][hr * 2 + 1] + b1;
                if (epi == 1) {                       // silu -> bf16 hi/lo out
                    v0 = v0 / (1.0f + __expf(-v0));
                    v1 = v1 / (1.0f + __expf(-v1));
                    __nv_bfloat162 h2, l2;
                    hilo2(v0, v1, h2, l2);
                    *(__nv_bfloat162*)&OutH[(size_t)row * Os + c] = h2;
                    *(__nv_bfloat162*)&OutL[(size_t)row * Os + c] = l2;
                } else {
                    if (epi == 2) {
                        v0 += resid[(size_t)row * 128 + c];
                        v1 += resid[(size_t)row * 128 + c + 1];
                    }
                    *(float2*)&Out[(size_t)row * Os + c] = make_float2(v0, v1);
                }
            }
        }
    }
}

// ---------------- fused edge pass: head-permuted B, lane-owned-head epilogue -------
// B column permutation: smem n-row (nt*8 + 2q + p) holds We^T logical row
// (h*64 + q*16 + nt*2 + p). Consequence: lane quad-slot q's 16 acc values are
// exactly head (h*4+q)'s 16 contiguous columns -> in-lane dot, float4 gathers,
// red_v4 scatters, no shuffles.
#define EAST 136
#define EDGE_SMEM 104448
__global__ void __launch_bounds__(256, 2) k_edge_mma(
        const float* __restrict__ ea_g, const int* __restrict__ ei, int E, int n) {
    extern __shared__ char sm[];
    __nv_bfloat16* Ah = (__nv_bfloat16*)sm;                    // 34816
    __nv_bfloat16* Al = (__nv_bfloat16*)(sm + 34816);          // 34816
    __nv_bfloat16* Bh = (__nv_bfloat16*)(sm + 69632);          // 17408
    __nv_bfloat16* Bl = (__nv_bfloat16*)(sm + 87040);          // 17408
    const __nv_bfloat16* WeTH = g_BtH + OFF_WE;
    const __nv_bfloat16* WeTL = g_BtL + OFF_WE;
    int tx = threadIdx.x, w = tx >> 5, lane = tx & 31;
    int e0 = blockIdx.x * 128;

    // convert EA tile fp32 -> bf16 hi/lo
    for (int idx = tx; idx < 4096; idx += 256) {
        int r = idx >> 5, c4 = idx & 31;
        float4 v = (e0 + r < E) ? ((const float4*)ea_g)[(size_t)(e0 + r) * 32 + c4]
                                : make_float4(0.f, 0.f, 0.f, 0.f);
        __nv_bfloat162 h01, l01, h23, l23;
        hilo2(v.x, v.y, h01, l01);
        hilo2(v.z, v.w, h23, l23);
        __nv_bfloat162* ph = (__nv_bfloat162*)&Ah[r * EAST + c4 * 4];
        ph[0] = h01; ph[1] = h23;
        __nv_bfloat162* pl = (__nv_bfloat162*)&Al[r * EAST + c4 * 4];
        pl[0] = l01; pl[1] = l23;
    }
    int arow = w * 16 + (lane & 15);
    int acol = (lane >> 4) << 3;
    int brl = lane & 7, bcol = (lane & 8) ? 8 : 0;
    int q = lane & 3;                        // lane's head slot within half

    // hoist per-row edge indices (rows owned by this thread's quad)
    int rowA = w * 16 + (lane >> 2);         // rr = 0
    int rowB = rowA + 8;                     // rr = 1
    int eA = e0 + rowA, eB = e0 + rowB;
    bool okA = (eA < E), okB = (eB < E);
    int eAc = okA ? eA : E - 1, eBc = okB ? eB : E - 1;
    int srcA = clampi(ei[eAc], 0, n - 1), dstA = clampi(ei[(size_t)E + eAc], 0, n - 1);
    int srcB = clampi(ei[eBc], 0, n - 1), dstB = clampi(ei[(size_t)E + eBc], 0, n - 1);

    for (int h = 0; h < 2; ++h) {
        if (h) __syncthreads();       // all warps done reading B(0) (MMA(0) complete)
        for (int i = tx; i < 2048; i += 256) {       // B half: 64 n x 128 k, hi+lo
            int half = i >> 10, j = i & 1023;
            int nr = j >> 4, k8 = (j & 15) * 8;
            int rt = nr & 7, nt = nr >> 3;
            int logical = ((rt >> 1) << 4) + (nt << 1) + (rt & 1);  // q*16 + nt*2 + p
            const __nv_bfloat16* s = half ? WeTL : WeTH;
            __nv_bfloat16* d = half ? Bl : Bh;
            *(uint4*)&d[nr * EAST + k8] =
                *(const uint4*)&s[(size_t)(h * 64 + logical) * 128 + k8];
        }
        __syncthreads();
        float acc[8][4];
#pragma unroll
        for (int nt = 0; nt < 8; ++nt) {
            acc[nt][0] = 0.f; acc[nt][1] = 0.f; acc[nt][2] = 0.f; acc[nt][3] = 0.f;
        }
        for (int kt = 0; kt < 8; ++kt) {
            int k0 = kt * 16;
            uint32_t ah[4], al[4];
            ldm_x4(ah, smem_u32(&Ah[arow * EAST + k0 + acol]));
            ldm_x4(al, smem_u32(&Al[arow * EAST + k0 + acol]));
#pragma unroll
            for (int nt = 0; nt < 8; ++nt) {
                uint32_t bh[2], bl[2];
                ldm_x2(bh, smem_u32(&Bh[(nt * 8 + brl) * EAST + k0 + bcol]));
                ldm_x2(bl, smem_u32(&Bl[(nt * 8 + brl) * EAST + k0 + bcol]));
                mma_bf16(acc[nt], ah, bh);
                mma_bf16(acc[nt], ah, bl);
                mma_bf16(acc[nt], al, bh);
            }
        }

        // lane-owned-head epilogue: head hd = h*4+q, cols h*64 + q*16 .. +15
#pragma unroll
        for (int rr = 0; rr < 2; ++rr) {
            bool ok = rr ? okB : okA;
            int src = rr ? srcB : srcA;
            int dst = rr ? dstB : dstA;
            int cbase = h * 64 + q * 16;
            const float4* qb = (const float4*)&g_qkvs[(size_t)dst * 512 + cbase];
            const float4* kb = (const float4*)&g_qkvs[(size_t)src * 512 + 128 + cbase];
            const float4* vb = (const float4*)&g_qkvs[(size_t)src * 512 + 256 + cbase];
            float logit = 0.f;
            float pv[16];
#pragma unroll
            for (int j = 0; j < 4; ++j) {
                float e0v = acc[j * 2 + 0][rr * 2 + 0];
                float e1v = acc[j * 2 + 0][rr * 2 + 1];
                float e2v = acc[j * 2 + 1][rr * 2 + 0];
                float e3v = acc[j * 2 + 1][rr * 2 + 1];
                float4 kq = kb[j];
                float4 qq = qb[j];
                float4 vv = vb[j];
                logit = fmaf(qq.x, kq.x + e0v, logit);
                logit = fmaf(qq.y, kq.y + e1v, logit);
                logit = fmaf(qq.z, kq.z + e2v, logit);
                logit = fmaf(qq.w, kq.w + e3v, logit);
                pv[j * 4 + 0] = vv.x + e0v;
                pv[j * 4 + 1] = vv.y + e1v;
                pv[j * 4 + 2] = vv.z + e2v;
                pv[j * 4 + 3] = vv.w + e3v;
            }
            float p = __expf(logit * 0.25f);   // 1/sqrt(16); shift-invariant softmax
            if (ok) {
                float* accp = &g_acc[(size_t)dst * 128 + cbase];
#pragma unroll
                for (int j = 0; j < 4; ++j)
                    red_v4(accp + j * 4, p * pv[j * 4 + 0], p * pv[j * 4 + 1],
                           p * pv[j * 4 + 2], p * pv[j * 4 + 3]);
                red_f32(&g_z[(size_t)dst * HH + h * 4 + q], p);
            }
        }
    }
}

// ---------------- K1: LayerNorm1 -> bf16 hi/lo, plus zero-init acc/z ----------------
__global__ void k_ln1(const float* __restrict__ x, const float* __restrict__ g,
                      const float* __restrict__ b, int n) {
    int row = blockIdx.x * 8 + (threadIdx.x >> 5);
    if (row >= n) return;
    int lane = threadIdx.x & 31;
    ((float4*)g_acc)[(size_t)row * 32 + lane] = make_float4(0.f, 0.f, 0.f, 0.f);
    if (lane < 8) g_z[(size_t)row * HH + lane] = 0.f;

    float4 v = ((const float4*)x)[(size_t)row * 32 + lane];
    float s  = v.x + v.y + v.z + v.w;
    float ss = fmaf(v.x, v.x, fmaf(v.y, v.y, fmaf(v.z, v.z, v.w * v.w)));
#pragma unroll
    for (int o = 16; o > 0; o >>= 1) {
        s  += __shfl_xor_sync(0xFFFFFFFFu, s, o);
        ss += __shfl_xor_sync(0xFFFFFFFFu, ss, o);
    }
    float mu  = s * (1.0f / 128.0f);
    float var = ss * (1.0f / 128.0f) - mu * mu;
    float r   = rsqrtf(var + 1e-5f);
    float4 gg = ((const float4*)g)[lane];
    float4 bb = ((const float4*)b)[lane];
    float o0 = (v.x - mu) * r * gg.x + bb.x;
    float o1 = (v.y - mu) * r * gg.y + bb.y;
    float o2 = (v.z - mu) * r * gg.z + bb.z;
    float o3 = (v.w - mu) * r * gg.w + bb.w;
    __nv_bfloat162 h01, l01, h23, l23;
    hilo2(o0, o1, h01, l01);
    hilo2(o2, o3, h23, l23);
    size_t base = (size_t)row * 128 + lane * 4;
    *(__nv_bfloat162*)&g_hH[base]     = h01;
    *(__nv_bfloat162*)&g_hH[base + 2] = h23;
    *(__nv_bfloat162*)&g_hL[base]     = l01;
    *(__nv_bfloat162*)&g_hL[base + 2] = l23;
}

// ---------------- K7: residual + LN2 -> x2 fp32, h2 bf16 hi/lo ----------------
__global__ void k_resid_ln2(const float* __restrict__ x, const float* __restrict__ alpha,
                            const float* __restrict__ g2, const float* __restrict__ b2,
                            int n) {
    int row = blockIdx.x * 8 + (threadIdx.x >> 5);
    if (row >= n) return;
    int lane = threadIdx.x & 31;
    float a = alpha[0];
    float4 xv = ((const float4*)x)[(size_t)row * 32 + lane];
    float4 av = ((const float4*)g_acc)[(size_t)row * 32 + lane];
    float4 sv = *(const float4*)&g_qkvs[(size_t)row * 512 + 384 + lane * 4];
    float inv = 1.0f / (g_z[(size_t)row * HH + (lane >> 2)] + 1e-16f);
    float4 o;
    o.x = xv.x + a * (av.x * inv + sv.x);
    o.y = xv.y + a * (av.y * inv + sv.y);
    o.z = xv.z + a * (av.z * inv + sv.z);
    o.w = xv.w + a * (av.w * inv + sv.w);
    ((float4*)g_x2)[(size_t)row * 32 + lane] = o;
    float s  = o.x + o.y + o.z + o.w;
    float ss = fmaf(o.x, o.x, fmaf(o.y, o.y, fmaf(o.z, o.z, o.w * o.w)));
#pragma unroll
    for (int off = 16; off > 0; off >>= 1) {
        s  += __shfl_xor_sync(0xFFFFFFFFu, s, off);
        ss += __shfl_xor_sync(0xFFFFFFFFu, ss, off);
    }
    float mu  = s * (1.0f / 128.0f);
    float var = ss * (1.0f / 128.0f) - mu * mu;
    float r   = rsqrtf(var + 1e-5f);
    float4 gg = ((const float4*)g2)[lane];
    float4 bb = ((const float4*)b2)[lane];
    float o0 = (o.x - mu) * r * gg.x + bb.x;
    float o1 = (o.y - mu) * r * gg.y + bb.y;
    float o2 = (o.z - mu) * r * gg.z + bb.z;
    float o3 = (o.w - mu) * r * gg.w + bb.w;
    __nv_bfloat162 h01, l01, h23, l23;
    hilo2(o0, o1, h01, l01);
    hilo2(o2, o3, h23, l23);
    size_t base = (size_t)row * 128 + lane * 4;
    *(__nv_bfloat162*)&g_h2H[base]     = h01;
    *(__nv_bfloat162*)&g_h2H[base + 2] = h23;
    *(__nv_bfloat162*)&g_h2L[base]     = l01;
    *(__nv_bfloat162*)&g_h2L[base + 2] = l23;
}

// ---------------- launch ----------------
extern "C" void kernel_launch(void* const* d_in, const int* in_sizes, int n_in,
                              void* d_out, int out_size) {
    const float* x      = (const float*)d_in[0];
    const float* eattr  = (const float*)d_in[1];
    const int*   ei     = (const int*)d_in[2];
    const float* Wq     = (const float*)d_in[3];
    const float* bq     = (const float*)d_in[4];
    const float* Wk     = (const float*)d_in[5];
    const float* bk     = (const float*)d_in[6];
    const float* Wv     = (const float*)d_in[7];
    const float* bv     = (const float*)d_in[8];
    const float* We     = (const float*)d_in[9];
    const float* Wskip  = (const float*)d_in[10];
    const float* bskip  = (const float*)d_in[11];
    const float* W1     = (const float*)d_in[12];
    const float* b1     = (const float*)d_in[13];
    const float* W2     = (const float*)d_in[14];
    const float* b2     = (const float*)d_in[15];
    const float* g1     = (const float*)d_in[16];
    const float* beta1  = (const float*)d_in[17];
    const float* g2     = (const float*)d_in[18];
    const float* beta2  = (const float*)d_in[19];
    const float* alpha  = (const float*)d_in[20];

    int n = in_sizes[0] / D;   // 50000
    int E = in_sizes[1] / D;   // 600000
    float* out = (float*)d_out;

    int rowTiles = (n + 127) / 128;       // 391
    int edgeTiles = (E + 127) / 128;      // 4688

    static bool init_done = false;
    static __nv_bfloat16 *pH, *pL, *phH, *phL, *ph2H, *ph2L, *puH, *puL;
    static float *pqkvs, *px2, *pbias;
    if (!init_done) {
        cudaFuncSetAttribute(k_edge_mma, cudaFuncAttributeMaxDynamicSharedMemorySize,
                             EDGE_SMEM);
        cudaFuncSetAttribute(k_dense_bf, cudaFuncAttributeMaxDynamicSharedMemorySize,
                             DENSE_SMEM);
        cudaGetSymbolAddress((void**)&pH, g_BtH);
        cudaGetSymbolAddress((void**)&pL, g_BtL);
        cudaGetSymbolAddress((void**)&phH, g_hH);
        cudaGetSymbolAddress((void**)&phL, g_hL);
        cudaGetSymbolAddress((void**)&ph2H, g_h2H);
        cudaGetSymbolAddress((void**)&ph2L, g_h2L);
        cudaGetSymbolAddress((void**)&puH, g_uH);
        cudaGetSymbolAddress((void**)&puL, g_uL);
        cudaGetSymbolAddress((void**)&pqkvs, g_qkvs);
        cudaGetSymbolAddress((void**)&px2, g_x2);
        cudaGetSymbolAddress((void**)&pbias, g_bqkvs);
        init_done = true;
    }

    k_preconv<<<(BT_TOTAL + 255) / 256, 256>>>(Wq, Wk, Wv, Wskip, We, W1, W2,
                                               bq, bk, bv, bskip);
    k_ln1<<<(n + 7) / 8, 256>>>(x, g1, beta1, n);

    // fused node projections -> g_qkvs [N][512]
    {
        dim3 grid(rowTiles, 4);
        k_dense_bf<<<grid, 256, DENSE_SMEM>>>(phH, phL, 128, pH + OFF_WQ, pL + OFF_WQ, 128,
                                              pbias, pqkvs, nullptr, nullptr, 512,
                                              nullptr, 0, n);
    }
    k_edge_mma<<<edgeTiles, 256, EDGE_SMEM>>>(eattr, ei, E, n);
    k_resid_ln2<<<(n + 7) / 8, 256>>>(x, alpha, g2, beta2, n);
    {
        dim3 grid(rowTiles, 4);
        k_dense_bf<<<grid, 256, DENSE_SMEM>>>(ph2H, ph2L, 128, pH + OFF_W1, pL + OFF_W1, 128,
                                              b1, nullptr, puH, puL, 512, nullptr, 1, n);
    }
    k_dense_bf<<<rowTiles, 256, DENSE_SMEM>>>(puH, puL, 512, pH + OFF_W2, pL + OFF_W2, 512,
                                              b2, out, nullptr, nullptr, 128, px2, 2, n);
}

// round 17
// speedup vs baseline: 1.4629x; 1.0602x over previous
#include <cuda_runtime.h>
#include <cuda_bf16.h>
#include <cstdint>

#define NN 50000
#define EE 600000
#define D 128
#define HH 8

// ---------------- scratch (device globals) ----------------
__device__ __nv_bfloat16 g_hH [(size_t)NN * D];
__device__ __nv_bfloat16 g_hL [(size_t)NN * D];
__device__ float g_qkvs[(size_t)NN * 512];         // q|k|v|skip
__device__ float g_z   [(size_t)NN * HH];
__device__ float g_acc [(size_t)NN * D];
__device__ float g_x2  [(size_t)NN * D];
__device__ __nv_bfloat16 g_h2H[(size_t)NN * D];
__device__ __nv_bfloat16 g_h2L[(size_t)NN * D];
__device__ __nv_bfloat16 g_uH [(size_t)NN * 4 * D];
__device__ __nv_bfloat16 g_uL [(size_t)NN * 4 * D];

// preconverted transposed weights, bf16 hi/lo, [n][k]
#define OFF_WQ 0
#define OFF_WE 65536
#define OFF_W1 81920
#define OFF_W2 147456
#define BT_TOTAL 212992
__device__ __nv_bfloat16 g_BtH[BT_TOTAL];
__device__ __nv_bfloat16 g_BtL[BT_TOTAL];
__device__ float g_bqkvs[512];

__device__ __forceinline__ int clampi(int v, int lo, int hi) {
    return v < lo ? lo : (v > hi ? hi : v);
}
__device__ __forceinline__ void red_f32(float* ptr, float a) {
    asm volatile("red.global.add.f32 [%0], %1;" :: "l"(ptr), "f"(a) : "memory");
}
__device__ __forceinline__ void red_v4(float* ptr, float a, float b, float c, float d) {
    asm volatile("red.global.v4.f32.add [%0], {%1,%2,%3,%4};"
                 :: "l"(ptr), "f"(a), "f"(b), "f"(c), "f"(d) : "memory");
}

// ---------------- mma helpers (sm_80+ PTX, arch-agnostic) ----------------
__device__ __forceinline__ uint32_t smem_u32(const void* p) {
    uint32_t a;
    asm("{ .reg .u64 t; cvta.to.shared.u64 t, %1; cvt.u32.u64 %0, t; }" : "=r"(a) : "l"(p));
    return a;
}
__device__ __forceinline__ void ldm_x4(uint32_t (&r)[4], uint32_t addr) {
    asm volatile("ldmatrix.sync.aligned.m8n8.x4.shared.b16 {%0,%1,%2,%3}, [%4];"
                 : "=r"(r[0]), "=r"(r[1]), "=r"(r[2]), "=r"(r[3]) : "r"(addr));
}
__device__ __forceinline__ void ldm_x2(uint32_t (&r)[2], uint32_t addr) {
    asm volatile("ldmatrix.sync.aligned.m8n8.x2.shared.b16 {%0,%1}, [%2];"
                 : "=r"(r[0]), "=r"(r[1]) : "r"(addr));
}
__device__ __forceinline__ void mma_bf16(float (&d)[4], const uint32_t (&a)[4],
                                         const uint32_t (&b)[2]) {
    asm volatile("mma.sync.aligned.m16n8k16.row.col.f32.bf16.bf16.f32 "
                 "{%0,%1,%2,%3}, {%4,%5,%6,%7}, {%8,%9}, {%0,%1,%2,%3};"
                 : "+f"(d[0]), "+f"(d[1]), "+f"(d[2]), "+f"(d[3])
                 : "r"(a[0]), "r"(a[1]), "r"(a[2]), "r"(a[3]), "r"(b[0]), "r"(b[1]));
}
// fp32 pair -> bf16 hi pair + lo pair
__device__ __forceinline__ void hilo2(float a, float b, __nv_bfloat162& h, __nv_bfloat162& l) {
    h = __float22bfloat162_rn(make_float2(a, b));
    float2 back = __bfloat1622float2(h);
    l = __float22bfloat162_rn(make_float2(a - back.x, b - back.y));
}

// ---------------- K0: preconvert weights + biases ----------------
__global__ void k_preconv(const float* __restrict__ Wq, const float* __restrict__ Wk,
                          const float* __restrict__ Wv, const float* __restrict__ Ws,
                          const float* __restrict__ We, const float* __restrict__ W1,
                          const float* __restrict__ W2,
                          const float* __restrict__ bq, const float* __restrict__ bk,
                          const float* __restrict__ bv, const float* __restrict__ bs) {
    int i = blockIdx.x * 256 + threadIdx.x;
    if (i < 512) {
        int w = i >> 7, j = i & 127;
        g_bqkvs[i] = (w == 0) ? bq[j] : (w == 1) ? bk[j] : (w == 2) ? bv[j] : bs[j];
    }
    if (i >= BT_TOTAL) return;
    float x;
    if (i < 65536) {
        int w = i >> 14, rem = i & 16383, nn = rem >> 7, kk = rem & 127;
        const float* W = (w == 0) ? Wq : (w == 1) ? Wk : (w == 2) ? Wv : Ws;
        x = W[kk * 128 + nn];
    } else if (i < 81920) {
        int rem = i - 65536, nn = rem >> 7, kk = rem & 127;
        x = We[kk * 128 + nn];
    } else if (i < 147456) {
        int rem = i - 81920, nn = rem >> 7, kk = rem & 127;
        x = W1[kk * 512 + nn];
    } else {
        int rem = i - 147456, nn = rem >> 9, kk = rem & 511;
        x = W2[kk * 128 + nn];
    }
    __nv_bfloat16 h = __float2bfloat16(x);
    g_BtH[i] = h;
    g_BtL[i] = __float2bfloat16(x - __bfloat162float(h));
}

// ---------------- generic dense GEMM with bf16 hi/lo inputs (R11-proven) ----------
#define DST 72
#define DENSE_SMEM 73728
__global__ void __launch_bounds__(256) k_dense_bf(
        const __nv_bfloat16* __restrict__ AH, const __nv_bfloat16* __restrict__ AL, int As,
        const __nv_bfloat16* __restrict__ BtHb, const __nv_bfloat16* __restrict__ BtLb,
        int K, const float* __restrict__ bias,
        float* __restrict__ Out, __nv_bfloat16* __restrict__ OutH,
        __nv_bfloat16* __restrict__ OutL, int Os,
        const float* __restrict__ resid, int epi, int M) {
    extern __shared__ char sm[];
    __nv_bfloat16* Ah = (__nv_bfloat16*)sm;
    __nv_bfloat16* Al = (__nv_bfloat16*)(sm + 18432);
    __nv_bfloat16* Bh = (__nv_bfloat16*)(sm + 36864);
    __nv_bfloat16* Bl = (__nv_bfloat16*)(sm + 55296);
    int tx = threadIdx.x, w = tx >> 5, lane = tx & 31;
    int row0 = blockIdx.x * 128, n0 = blockIdx.y * 128;
    const __nv_bfloat16* BH = BtHb + (size_t)n0 * K;
    const __nv_bfloat16* BL = BtLb + (size_t)n0 * K;
    float acc[16][4];
#pragma unroll
    for (int nt = 0; nt < 16; ++nt) {
        acc[nt][0] = 0.f; acc[nt][1] = 0.f; acc[nt][2] = 0.f; acc[nt][3] = 0.f;
    }
    int arow = w * 16 + (lane & 15);
    int acol = (lane >> 4) << 3;
    int brl = lane & 7, bcol = (lane & 8) ? 8 : 0;

    for (int kc = 0; kc < K; kc += 64) {
        __syncthreads();
        for (int i = tx; i < 2048; i += 256) {       // A: 128 rows x 64 k, hi+lo
            int half = i >> 10, j = i & 1023;
            int r = j >> 3, k8 = (j & 7) * 8;
            const __nv_bfloat16* s = half ? AL : AH;
            __nv_bfloat16* d = half ? Al : Ah;
            uint4 val = (row0 + r < M)
                ? *(const uint4*)&s[(size_t)(row0 + r) * As + kc + k8]
                : make_uint4(0u, 0u, 0u, 0u);
            *(uint4*)&d[r * DST + k8] = val;
        }
        for (int i = tx; i < 2048; i += 256) {       // B: 128 n x 64 k, hi+lo
            int half = i >> 10, j = i & 1023;
            int nr = j >> 3, k8 = (j & 7) * 8;
            const __nv_bfloat16* s = half ? BL : BH;
            __nv_bfloat16* d = half ? Bl : Bh;
            *(uint4*)&d[nr * DST + k8] = *(const uint4*)&s[(size_t)nr * K + kc + k8];
        }
        __syncthreads();
        for (int kt = 0; kt < 4; ++kt) {
            int k0 = kt * 16;
            uint32_t ah[4], al[4];
            ldm_x4(ah, smem_u32(&Ah[arow * DST + k0 + acol]));
            ldm_x4(al, smem_u32(&Al[arow * DST + k0 + acol]));
#pragma unroll
            for (int nt = 0; nt < 16; ++nt) {
                uint32_t bh[2], bl[2];
                ldm_x2(bh, smem_u32(&Bh[(nt * 8 + brl) * DST + k0 + bcol]));
                ldm_x2(bl, smem_u32(&Bl[(nt * 8 + brl) * DST + k0 + bcol]));
                mma_bf16(acc[nt], ah, bh);
                mma_bf16(acc[nt], ah, bl);
                mma_bf16(acc[nt], al, bh);
            }
        }
    }
    int rbase = row0 + w * 16 + (lane >> 2);
    int cb = (lane & 3) * 2;
#pragma unroll
    for (int nt = 0; nt < 16; ++nt) {
        int c = n0 + nt * 8 + cb;
        float b0 = bias[c], b1 = bias[c + 1];
#pragma unroll
        for (int hr = 0; hr < 2; ++hr) {
            int row = rbase + hr * 8;
            if (row < M) {
                float v0 = acc[nt][hr * 2 + 0] + b0;
                float v1 = acc[nt][hr * 2 + 1] + b1;
                if (epi == 1) {                       // silu -> bf16 hi/lo out
                    v0 = v0 / (1.0f + __expf(-v0));
                    v1 = v1 / (1.0f + __expf(-v1));
                    __nv_bfloat162 h2, l2;
                    hilo2(v0, v1, h2, l2);
                    *(__nv_bfloat162*)&OutH[(size_t)row * Os + c] = h2;
                    *(__nv_bfloat162*)&OutL[(size_t)row * Os + c] = l2;
                } else {
                    if (epi == 2) {
                        v0 += resid[(size_t)row * 128 + c];
                        v1 += resid[(size_t)row * 128 + c + 1];
                    }
                    *(float2*)&Out[(size_t)row * Os + c] = make_float2(v0, v1);
                }
            }
        }
    }
}

// ---------------- fused edge pass: A single-bf16, B hi/lo 2-term, 3 CTAs/SM --------
// B column permutation (R16): smem n-row (nt*8 + 2q + p) holds We^T logical row
// (h*64 + q*16 + nt*2 + p) -> lane quad-slot q owns head (h*4+q)'s 16 contiguous cols.
// Precision: dropping A-lo puts ~1.5e-3 rel on e (additive term on k,v ~0.5, output
// dominated by x ~1) -> expected final rel_err ~1e-4..4e-4, inside the 1e-3 gate.
#define EAST 136
#define EDGE_SMEM 69632
__global__ void __launch_bounds__(256, 3) k_edge_mma(
        const float* __restrict__ ea_g, const int* __restrict__ ei, int E, int n) {
    extern __shared__ char sm[];
    __nv_bfloat16* Ah = (__nv_bfloat16*)sm;                    // 34816
    __nv_bfloat16* Bh = (__nv_bfloat16*)(sm + 34816);          // 17408
    __nv_bfloat16* Bl = (__nv_bfloat16*)(sm + 52224);          // 17408
    const __nv_bfloat16* WeTH = g_BtH + OFF_WE;
    const __nv_bfloat16* WeTL = g_BtL + OFF_WE;
    int tx = threadIdx.x, w = tx >> 5, lane = tx & 31;
    int e0 = blockIdx.x * 128;

    // convert EA tile fp32 -> bf16 (single, rn)
    for (int idx = tx; idx < 4096; idx += 256) {
        int r = idx >> 5, c4 = idx & 31;
        float4 v = (e0 + r < E) ? ((const float4*)ea_g)[(size_t)(e0 + r) * 32 + c4]
                                : make_float4(0.f, 0.f, 0.f, 0.f);
        __nv_bfloat162* ph = (__nv_bfloat162*)&Ah[r * EAST + c4 * 4];
        ph[0] = __float22bfloat162_rn(make_float2(v.x, v.y));
        ph[1] = __float22bfloat162_rn(make_float2(v.z, v.w));
    }
    int arow = w * 16 + (lane & 15);
    int acol = (lane >> 4) << 3;
    int brl = lane & 7, bcol = (lane & 8) ? 8 : 0;
    int q = lane & 3;                        // lane's head slot within half

    // hoist per-row edge indices (rows owned by this thread's quad)
    int rowA = w * 16 + (lane >> 2);         // rr = 0
    int rowB = rowA + 8;                     // rr = 1
    int eA = e0 + rowA, eB = e0 + rowB;
    bool okA = (eA < E), okB = (eB < E);
    int eAc = okA ? eA : E - 1, eBc = okB ? eB : E - 1;
    int srcA = clampi(ei[eAc], 0, n - 1), dstA = clampi(ei[(size_t)E + eAc], 0, n - 1);
    int srcB = clampi(ei[eBc], 0, n - 1), dstB = clampi(ei[(size_t)E + eBc], 0, n - 1);

    for (int h = 0; h < 2; ++h) {
        if (h) __syncthreads();       // all warps done reading B(0) (MMA(0) complete)
        for (int i = tx; i < 2048; i += 256) {       // B half: 64 n x 128 k, hi+lo
            int half = i >> 10, j = i & 1023;
            int nr = j >> 4, k8 = (j & 15) * 8;
            int rt = nr & 7, nt = nr >> 3;
            int logical = ((rt >> 1) << 4) + (nt << 1) + (rt & 1);  // q*16 + nt*2 + p
            const __nv_bfloat16* s = half ? WeTL : WeTH;
            __nv_bfloat16* d = half ? Bl : Bh;
            *(uint4*)&d[nr * EAST + k8] =
                *(const uint4*)&s[(size_t)(h * 64 + logical) * 128 + k8];
        }
        __syncthreads();
        float acc[8][4];
#pragma unroll
        for (int nt = 0; nt < 8; ++nt) {
            acc[nt][0] = 0.f; acc[nt][1] = 0.f; acc[nt][2] = 0.f; acc[nt][3] = 0.f;
        }
        for (int kt = 0; kt < 8; ++kt) {
            int k0 = kt * 16;
            uint32_t ah[4];
            ldm_x4(ah, smem_u32(&Ah[arow * EAST + k0 + acol]));
#pragma unroll
            for (int nt = 0; nt < 8; ++nt) {
                uint32_t bh[2], bl[2];
                ldm_x2(bh, smem_u32(&Bh[(nt * 8 + brl) * EAST + k0 + bcol]));
                ldm_x2(bl, smem_u32(&Bl[(nt * 8 + brl) * EAST + k0 + bcol]));
                mma_bf16(acc[nt], ah, bh);
                mma_bf16(acc[nt], ah, bl);
            }
        }

        // lane-owned-head epilogue: head hd = h*4+q, cols h*64 + q*16 .. +15
#pragma unroll
        for (int rr = 0; rr < 2; ++rr) {
            bool ok = rr ? okB : okA;
            int src = rr ? srcB : srcA;
            int dst = rr ? dstB : dstA;
            int cbase = h * 64 + q * 16;
            const float4* qb = (const float4*)&g_qkvs[(size_t)dst * 512 + cbase];
            const float4* kb = (const float4*)&g_qkvs[(size_t)src * 512 + 128 + cbase];
            const float4* vb = (const float4*)&g_qkvs[(size_t)src * 512 + 256 + cbase];
            float logit = 0.f;
            float pv[16];
#pragma unroll
            for (int j = 0; j < 4; ++j) {
                float e0v = acc[j * 2 + 0][rr * 2 + 0];
                float e1v = acc[j * 2 + 0][rr * 2 + 1];
                float e2v = acc[j * 2 + 1][rr * 2 + 0];
                float e3v = acc[j * 2 + 1][rr * 2 + 1];
                float4 kq = kb[j];
                float4 qq = qb[j];
                float4 vv = vb[j];
                logit = fmaf(qq.x, kq.x + e0v, logit);
                logit = fmaf(qq.y, kq.y + e1v, logit);
                logit = fmaf(qq.z, kq.z + e2v, logit);
                logit = fmaf(qq.w, kq.w + e3v, logit);
                pv[j * 4 + 0] = vv.x + e0v;
                pv[j * 4 + 1] = vv.y + e1v;
                pv[j * 4 + 2] = vv.z + e2v;
                pv[j * 4 + 3] = vv.w + e3v;
            }
            float p = __expf(logit * 0.25f);   // 1/sqrt(16); shift-invariant softmax
            if (ok) {
                float* accp = &g_acc[(size_t)dst * 128 + cbase];
#pragma unroll
                for (int j = 0; j < 4; ++j)
                    red_v4(accp + j * 4, p * pv[j * 4 + 0], p * pv[j * 4 + 1],
                           p * pv[j * 4 + 2], p * pv[j * 4 + 3]);
                red_f32(&g_z[(size_t)dst * HH + h * 4 + q], p);
            }
        }
    }
}

// ---------------- K1: LayerNorm1 -> bf16 hi/lo, plus zero-init acc/z ----------------
__global__ void k_ln1(const float* __restrict__ x, const float* __restrict__ g,
                      const float* __restrict__ b, int n) {
    int row = blockIdx.x * 8 + (threadIdx.x >> 5);
    if (row >= n) return;
    int lane = threadIdx.x & 31;
    ((float4*)g_acc)[(size_t)row * 32 + lane] = make_float4(0.f, 0.f, 0.f, 0.f);
    if (lane < 8) g_z[(size_t)row * HH + lane] = 0.f;

    float4 v = ((const float4*)x)[(size_t)row * 32 + lane];
    float s  = v.x + v.y + v.z + v.w;
    float ss = fmaf(v.x, v.x, fmaf(v.y, v.y, fmaf(v.z, v.z, v.w * v.w)));
#pragma unroll
    for (int o = 16; o > 0; o >>= 1) {
        s  += __shfl_xor_sync(0xFFFFFFFFu, s, o);
        ss += __shfl_xor_sync(0xFFFFFFFFu, ss, o);
    }
    float mu  = s * (1.0f / 128.0f);
    float var = ss * (1.0f / 128.0f) - mu * mu;
    float r   = rsqrtf(var + 1e-5f);
    float4 gg = ((const float4*)g)[lane];
    float4 bb = ((const float4*)b)[lane];
    float o0 = (v.x - mu) * r * gg.x + bb.x;
    float o1 = (v.y - mu) * r * gg.y + bb.y;
    float o2 = (v.z - mu) * r * gg.z + bb.z;
    float o3 = (v.w - mu) * r * gg.w + bb.w;
    __nv_bfloat162 h01, l01, h23, l23;
    hilo2(o0, o1, h01, l01);
    hilo2(o2, o3, h23, l23);
    size_t base = (size_t)row * 128 + lane * 4;
    *(__nv_bfloat162*)&g_hH[base]     = h01;
    *(__nv_bfloat162*)&g_hH[base + 2] = h23;
    *(__nv_bfloat162*)&g_hL[base]     = l01;
    *(__nv_bfloat162*)&g_hL[base + 2] = l23;
}

// ---------------- K7: residual + LN2 -> x2 fp32, h2 bf16 hi/lo ----------------
__global__ void k_resid_ln2(const float* __restrict__ x, const float* __restrict__ alpha,
                            const float* __restrict__ g2, const float* __restrict__ b2,
                            int n) {
    int row = blockIdx.x * 8 + (threadIdx.x >> 5);
    if (row >= n) return;
    int lane = threadIdx.x & 31;
    float a = alpha[0];
    float4 xv = ((const float4*)x)[(size_t)row * 32 + lane];
    float4 av = ((const float4*)g_acc)[(size_t)row * 32 + lane];
    float4 sv = *(const float4*)&g_qkvs[(size_t)row * 512 + 384 + lane * 4];
    float inv = 1.0f / (g_z[(size_t)row * HH + (lane >> 2)] + 1e-16f);
    float4 o;
    o.x = xv.x + a * (av.x * inv + sv.x);
    o.y = xv.y + a * (av.y * inv + sv.y);
    o.z = xv.z + a * (av.z * inv + sv.z);
    o.w = xv.w + a * (av.w * inv + sv.w);
    ((float4*)g_x2)[(size_t)row * 32 + lane] = o;
    float s  = o.x + o.y + o.z + o.w;
    float ss = fmaf(o.x, o.x, fmaf(o.y, o.y, fmaf(o.z, o.z, o.w * o.w)));
#pragma unroll
    for (int off = 16; off > 0; off >>= 1) {
        s  += __shfl_xor_sync(0xFFFFFFFFu, s, off);
        ss += __shfl_xor_sync(0xFFFFFFFFu, ss, off);
    }
    float mu  = s * (1.0f / 128.0f);
    float var = ss * (1.0f / 128.0f) - mu * mu;
    float r   = rsqrtf(var + 1e-5f);
    float4 gg = ((const float4*)g2)[lane];
    float4 bb = ((const float4*)b2)[lane];
    float o0 = (o.x - mu) * r * gg.x + bb.x;
    float o1 = (o.y - mu) * r * gg.y + bb.y;
    float o2 = (o.z - mu) * r * gg.z + bb.z;
    float o3 = (o.w - mu) * r * gg.w + bb.w;
    __nv_bfloat162 h01, l01, h23, l23;
    hilo2(o0, o1, h01, l01);
    hilo2(o2, o3, h23, l23);
    size_t base = (size_t)row * 128 + lane * 4;
    *(__nv_bfloat162*)&g_h2H[base]     = h01;
    *(__nv_bfloat162*)&g_h2H[base + 2] = h23;
    *(__nv_bfloat162*)&g_h2L[base]     = l01;
    *(__nv_bfloat162*)&g_h2L[base + 2] = l23;
}

// ---------------- launch ----------------
extern "C" void kernel_launch(void* const* d_in, const int* in_sizes, int n_in,
                              void* d_out, int out_size) {
    const float* x      = (const float*)d_in[0];
    const float* eattr  = (const float*)d_in[1];
    const int*   ei     = (const int*)d_in[2];
    const float* Wq     = (const float*)d_in[3];
    const float* bq     = (const float*)d_in[4];
    const float* Wk     = (const float*)d_in[5];
    const float* bk     = (const float*)d_in[6];
    const float* Wv     = (const float*)d_in[7];
    const float* bv     = (const float*)d_in[8];
    const float* We     = (const float*)d_in[9];
    const float* Wskip  = (const float*)d_in[10];
    const float* bskip  = (const float*)d_in[11];
    const float* W1     = (const float*)d_in[12];
    const float* b1     = (const float*)d_in[13];
    const float* W2     = (const float*)d_in[14];
    const float* b2     = (const float*)d_in[15];
    const float* g1     = (const float*)d_in[16];
    const float* beta1  = (const float*)d_in[17];
    const float* g2     = (const float*)d_in[18];
    const float* beta2  = (const float*)d_in[19];
    const float* alpha  = (const float*)d_in[20];

    int n = in_sizes[0] / D;   // 50000
    int E = in_sizes[1] / D;   // 600000
    float* out = (float*)d_out;

    int rowTiles = (n + 127) / 128;       // 391
    int edgeTiles = (E + 127) / 128;      // 4688

    static bool init_done = false;
    static __nv_bfloat16 *pH, *pL, *phH, *phL, *ph2H, *ph2L, *puH, *puL;
    static float *pqkvs, *px2, *pbias;
    if (!init_done) {
        cudaFuncSetAttribute(k_edge_mma, cudaFuncAttributeMaxDynamicSharedMemorySize,
                             EDGE_SMEM);
        cudaFuncSetAttribute(k_dense_bf, cudaFuncAttributeMaxDynamicSharedMemorySize,
                             DENSE_SMEM);
        cudaGetSymbolAddress((void**)&pH, g_BtH);
        cudaGetSymbolAddress((void**)&pL, g_BtL);
        cudaGetSymbolAddress((void**)&phH, g_hH);
        cudaGetSymbolAddress((void**)&phL, g_hL);
        cudaGetSymbolAddress((void**)&ph2H, g_h2H);
        cudaGetSymbolAddress((void**)&ph2L, g_h2L);
        cudaGetSymbolAddress((void**)&puH, g_uH);
        cudaGetSymbolAddress((void**)&puL, g_uL);
        cudaGetSymbolAddress((void**)&pqkvs, g_qkvs);
        cudaGetSymbolAddress((void**)&px2, g_x2);
        cudaGetSymbolAddress((void**)&pbias, g_bqkvs);
        init_done = true;
    }

    k_preconv<<<(BT_TOTAL + 255) / 256, 256>>>(Wq, Wk, Wv, Wskip, We, W1, W2,
                                               bq, bk, bv, bskip);
    k_ln1<<<(n + 7) / 8, 256>>>(x, g1, beta1, n);

    // fused node projections -> g_qkvs [N][512]
    {
        dim3 grid(rowTiles, 4);
        k_dense_bf<<<grid, 256, DENSE_SMEM>>>(phH, phL, 128, pH + OFF_WQ, pL + OFF_WQ, 128,
                                              pbias, pqkvs, nullptr, nullptr, 512,
                                              nullptr, 0, n);
    }
    k_edge_mma<<<edgeTiles, 256, EDGE_SMEM>>>(eattr, ei, E, n);
    k_resid_ln2<<<(n + 7) / 8, 256>>>(x, alpha, g2, beta2, n);
    {
        dim3 grid(rowTiles, 4);
        k_dense_bf<<<grid, 256, DENSE_SMEM>>>(ph2H, ph2L, 128, pH + OFF_W1, pL + OFF_W1, 128,
                                              b1, nullptr, puH, puL, 512, nullptr, 1, n);
    }
    k_dense_bf<<<rowTiles, 256, DENSE_SMEM>>>(puH, puL, 512, pH + OFF_W2, pL + OFF_W2, 512,
                                              b2, out, nullptr, nullptr, 128, px2, 2, n);
}